// round 6
// baseline (speedup 1.0000x reference)
#include <cuda_runtime.h>
#include <cstdint>

#define NN 100000
#define EE 1600000
#define FF 128
#define HH 64
#define GG 128
#define CC 10
#define EPS 1e-5f
#define FULLMASK 0xffffffffu

// ---------------- device scratch ----------------
__device__ __align__(16) float g_h1[NN * HH];
__device__ __align__(16) float g_h2[NN * HH];
__device__ __align__(16) float g_hw[NN * HH];
__device__ int   g_degcnt[NN];
__device__ int   g_counts[NN];
__device__ int   g_offs[NN];
__device__ int   g_cursor[NN];
__device__ float g_dinv[NN];
__device__ int   g_src[EE];
__device__ float g_w[EE];
__device__ int   g_blockSums[128];
__device__ float g_sum[FF];
__device__ float g_sumsq[FF];
__device__ __align__(16) float g_Wp[FF * HH];
__device__ __align__(16) float g_c1[HH];
__device__ __align__(16) float g_Wc[HH * HH];
__device__ __align__(16) float g_c2[HH];
__device__ __align__(16) float g_hg[GG * HH];
__device__ int   g_ticket;

__device__ __forceinline__ float* buf(int sel) { return sel ? g_h2 : g_h1; }

// ---------------- f32x2 packed helpers ----------------
__device__ __forceinline__ unsigned long long pack2(float a, float b) {
    unsigned long long r;
    asm("mov.b64 %0, {%1, %2};" : "=l"(r) : "f"(a), "f"(b));
    return r;
}
__device__ __forceinline__ unsigned long long packdup(float a) {
    unsigned long long r;
    asm("mov.b64 %0, {%1, %1};" : "=l"(r) : "f"(a));
    return r;
}
__device__ __forceinline__ void unpack2(unsigned long long v, float& a, float& b) {
    asm("mov.b64 {%0, %1}, %2;" : "=f"(a), "=f"(b) : "l"(v));
}
__device__ __forceinline__ unsigned long long fma2(unsigned long long a, unsigned long long b,
                                                   unsigned long long c) {
    unsigned long long d;
    asm("fma.rn.f32x2 %0, %1, %2, %3;" : "=l"(d) : "l"(a), "l"(b), "l"(c));
    return d;
}

// ---------------- init ----------------
__global__ void zero_all(int n) {
    int i = blockIdx.x * blockDim.x + threadIdx.x;
    int st = gridDim.x * blockDim.x;
    for (int k = i; k < n; k += st) { g_degcnt[k] = 0; g_counts[k] = 0; }
    for (int k = i; k < GG * HH; k += st) g_hg[k] = 0.f;
    for (int k = i; k < FF; k += st) { g_sum[k] = 0.f; g_sumsq[k] = 0.f; }
    if (i == 0) g_ticket = 0;
}

// ---------------- CSR build (int32 indices) ----------------
__global__ void edge_count(const int* __restrict__ ei, int e) {
    int idx = blockIdx.x * blockDim.x + threadIdx.x;
    if (idx >= e) return;
    int r = ei[idx];
    int c = ei[idx + e];
    if (r != c) {
        atomicAdd(&g_degcnt[r], 1);
        atomicAdd(&g_counts[c], 1);
    }
}

__global__ void scan_blocks(int n) {
    __shared__ int tmp[1024];
    int i = blockIdx.x * 1024 + threadIdx.x;
    int v = (i < n) ? g_counts[i] : 0;
    tmp[threadIdx.x] = v;
    __syncthreads();
    for (int d = 1; d < 1024; d <<= 1) {
        int t = (threadIdx.x >= d) ? tmp[threadIdx.x - d] : 0;
        __syncthreads();
        tmp[threadIdx.x] += t;
        __syncthreads();
    }
    if (i < n) g_offs[i] = tmp[threadIdx.x] - v;   // exclusive within block
    if (threadIdx.x == 1023) g_blockSums[blockIdx.x] = tmp[1023];
}

// fused: block-sum prefix (was scan_top) + offset add + cursor + dinv (was compute_dinv)
__global__ void scan_add(int n, int nblk) {
    __shared__ int bs[128];
    int tid = threadIdx.x;
    if (tid < nblk) bs[tid] = g_blockSums[tid];
    __syncthreads();
    int i = blockIdx.x * blockDim.x + tid;
    if (i < n) {
        int blk = i >> 10;
        int add = 0;
        for (int j = 0; j < blk; j++) add += bs[j];
        int off = g_offs[i] + add;
        g_offs[i] = off;
        g_cursor[i] = off;
        g_dinv[i] = rsqrtf((float)g_degcnt[i] + 1.0f);
    }
}

__global__ void fill_edges(const int* __restrict__ ei, int e) {
    int idx = blockIdx.x * blockDim.x + threadIdx.x;
    if (idx >= e) return;
    int r = ei[idx];
    int c = ei[idx + e];
    if (r != c) {
        int p = atomicAdd(&g_cursor[c], 1);
        g_src[p] = r;
        g_w[p] = g_dinv[r] * g_dinv[c];
    }
}

// ---------------- shared prep helper: fold BN (stats in g_sum/g_sumsq) into next conv W ----------------
__device__ void prep_conv_dev(const float* __restrict__ Wc, const float* __restrict__ g,
                              const float* __restrict__ b, float inv_n, int tid) {
    __shared__ float scale[HH], beta[HH];
    if (tid < HH) {
        float m = g_sum[tid] * inv_n;
        float v = g_sumsq[tid] * inv_n - m * m;
        float s = rsqrtf(v + EPS) * g[tid];
        scale[tid] = s;
        beta[tid]  = b[tid] - m * s;
    }
    __syncthreads();
    for (int i = tid; i < HH * HH; i += 256) g_Wc[i] = scale[i >> 6] * Wc[i];
    if (tid < HH) {
        float c = 0.f;
        for (int k = 0; k < HH; k++) c += beta[k] * Wc[k * HH + tid];
        g_c2[tid] = c;
        g_sum[tid] = 0.f;      // reset for next stats stage
        g_sumsq[tid] = 0.f;
    }
    if (tid == 0) g_ticket = 0;
}

// ---------------- stats over x + last-block prep of g_Wp/g_c1 ----------------
__global__ __launch_bounds__(256) void stats_prep_x(const float* __restrict__ x, int n,
        const float* __restrict__ Wf, const float* __restrict__ g, const float* __restrict__ b,
        float inv_n) {
    __shared__ float red[2][FF];
    __shared__ int isLast;
    int tid = threadIdx.x;
    int col = tid & 127, rh = tid >> 7;
    float s = 0.f, q = 0.f;
    for (int row = blockIdx.x * 2 + rh; row < n; row += gridDim.x * 2) {
        float v = x[(size_t)row * FF + col];
        s += v; q += v * v;
    }
    red[rh][col] = s; __syncthreads();
    if (rh == 0) atomicAdd(&g_sum[col], s + red[1][col]);
    __syncthreads();
    red[rh][col] = q; __syncthreads();
    if (rh == 0) atomicAdd(&g_sumsq[col], q + red[1][col]);
    __threadfence();
    __syncthreads();
    if (tid == 0) isLast = (atomicAdd(&g_ticket, 1) == (int)gridDim.x - 1);
    __syncthreads();
    if (!isLast) return;
    __shared__ float scale[FF], beta[FF];
    if (tid < FF) {
        float m = g_sum[tid] * inv_n;
        float va = g_sumsq[tid] * inv_n - m * m;
        float sc = rsqrtf(va + EPS) * g[tid];
        scale[tid] = sc;
        beta[tid]  = b[tid] - m * sc;
    }
    __syncthreads();
    for (int i = tid; i < FF * HH; i += 256) g_Wp[i] = scale[i >> 6] * Wf[i];
    if (tid < HH) {
        float c = 0.f;
        for (int k = 0; k < FF; k++) c += beta[k] * Wf[k * HH + tid];
        g_c1[tid] = c;
    }
    if (tid < FF) { g_sum[tid] = 0.f; g_sumsq[tid] = 0.f; }
    if (tid == 0) g_ticket = 0;
}

// ---------------- mm_feat: [n,128] @ g_Wp[128,64] + c1, relu -> g_h1; fused stats + prep(conv0) ----------------
__global__ __launch_bounds__(256) void mm_feat(const float* __restrict__ x, int n,
        const float* __restrict__ Wnext, const float* __restrict__ bn_g,
        const float* __restrict__ bn_b, float inv_n) {
    extern __shared__ float smem[];
    float* xsT = smem;                 // [128 k][130]
    float* ws  = smem + 128 * 130;     // [128 k][64]
    __shared__ float red[8][HH];
    __shared__ int isLast;
    float* out = g_h1;
    int tid = threadIdx.x;
    int r0 = blockIdx.x * 128;

    for (int i = tid; i < 128 * 16; i += 256)
        ((float4*)ws)[i] = ((const float4*)g_Wp)[i];
    for (int p = 0; p < 16; p++) {
        int idx = p * 256 + tid;
        int k4 = idx & 31;         // K/4 = 32
        int row = idx >> 5;        // 0..127
        int gr = r0 + row;
        float4 v = make_float4(0.f, 0.f, 0.f, 0.f);
        if (gr < n) v = ((const float4*)(x + (size_t)gr * FF))[k4];
        xsT[(4 * k4 + 0) * 130 + row] = v.x;
        xsT[(4 * k4 + 1) * 130 + row] = v.y;
        xsT[(4 * k4 + 2) * 130 + row] = v.z;
        xsT[(4 * k4 + 3) * 130 + row] = v.w;
    }
    __syncthreads();

    int cg = tid & 31;   // cols cg and cg+32
    int rg = tid >> 5;   // rows rg*16 .. rg*16+15
    unsigned long long a0[8], a1[8];
    {
        unsigned long long b0 = packdup(g_c1[cg]);
        unsigned long long b1 = packdup(g_c1[cg + 32]);
#pragma unroll
        for (int i = 0; i < 8; i++) { a0[i] = b0; a1[i] = b1; }
    }
    for (int k = 0; k < 128; k++) {
        unsigned long long w0 = packdup(ws[k * 64 + cg]);
        unsigned long long w1 = packdup(ws[k * 64 + cg + 32]);
        const unsigned long long* xp = (const unsigned long long*)(xsT + k * 130 + rg * 16);
#pragma unroll
        for (int i = 0; i < 8; i++) {
            unsigned long long xv = xp[i];
            a0[i] = fma2(xv, w0, a0[i]);
            a1[i] = fma2(xv, w1, a1[i]);
        }
    }
    float s0 = 0.f, q0 = 0.f, s1 = 0.f, q1 = 0.f;
#pragma unroll
    for (int i = 0; i < 8; i++) {
        float v0, v1, u0, u1;
        unpack2(a0[i], v0, v1);
        unpack2(a1[i], u0, u1);
        v0 = fmaxf(v0, 0.f); v1 = fmaxf(v1, 0.f);
        u0 = fmaxf(u0, 0.f); u1 = fmaxf(u1, 0.f);
        int row = r0 + rg * 16 + 2 * i;
        if (row < n) {
            out[(size_t)row * HH + cg] = v0;
            out[(size_t)row * HH + cg + 32] = u0;
            s0 += v0; q0 += v0 * v0; s1 += u0; q1 += u0 * u0;
        }
        if (row + 1 < n) {
            out[(size_t)(row + 1) * HH + cg] = v1;
            out[(size_t)(row + 1) * HH + cg + 32] = u1;
            s0 += v1; q0 += v1 * v1; s1 += u1; q1 += u1 * u1;
        }
    }
    // block stats reduce + atomic
    red[rg][cg] = s0; red[rg][cg + 32] = s1;
    __syncthreads();
    if (tid < HH) { float s = 0.f; for (int r = 0; r < 8; r++) s += red[r][tid]; atomicAdd(&g_sum[tid], s); }
    __syncthreads();
    red[rg][cg] = q0; red[rg][cg + 32] = q1;
    __syncthreads();
    if (tid < HH) { float q = 0.f; for (int r = 0; r < 8; r++) q += red[r][tid]; atomicAdd(&g_sumsq[tid], q); }
    __threadfence();
    __syncthreads();
    if (tid == 0) isLast = (atomicAdd(&g_ticket, 1) == (int)gridDim.x - 1);
    __syncthreads();
    if (isLast) prep_conv_dev(Wnext, bn_g, bn_b, inv_n, tid);
}

// ---------------- mm_conv: buf(isel)[n,64] @ g_Wc + c2 -> g_hw (no relu, no stats) ----------------
__global__ __launch_bounds__(256) void mm_conv(int isel, int n) {
    extern __shared__ float smem[];
    float* xsT = smem;               // [64 k][130]
    float* ws  = smem + 64 * 130;    // [64 k][64]
    const float* in = buf(isel);
    float* out = g_hw;
    int tid = threadIdx.x;
    int r0 = blockIdx.x * 128;

    for (int i = tid; i < 64 * 16; i += 256)
        ((float4*)ws)[i] = ((const float4*)g_Wc)[i];
    for (int p = 0; p < 8; p++) {
        int idx = p * 256 + tid;
        int k4 = idx & 15;          // K/4 = 16
        int row = idx >> 4;         // 0..127
        int gr = r0 + row;
        float4 v = make_float4(0.f, 0.f, 0.f, 0.f);
        if (gr < n) v = ((const float4*)(in + (size_t)gr * HH))[k4];
        xsT[(4 * k4 + 0) * 130 + row] = v.x;
        xsT[(4 * k4 + 1) * 130 + row] = v.y;
        xsT[(4 * k4 + 2) * 130 + row] = v.z;
        xsT[(4 * k4 + 3) * 130 + row] = v.w;
    }
    __syncthreads();

    int cg = tid & 31;
    int rg = tid >> 5;
    unsigned long long a0[8], a1[8];
    {
        unsigned long long b0 = packdup(g_c2[cg]);
        unsigned long long b1 = packdup(g_c2[cg + 32]);
#pragma unroll
        for (int i = 0; i < 8; i++) { a0[i] = b0; a1[i] = b1; }
    }
    for (int k = 0; k < 64; k++) {
        unsigned long long w0 = packdup(ws[k * 64 + cg]);
        unsigned long long w1 = packdup(ws[k * 64 + cg + 32]);
        const unsigned long long* xp = (const unsigned long long*)(xsT + k * 130 + rg * 16);
#pragma unroll
        for (int i = 0; i < 8; i++) {
            unsigned long long xv = xp[i];
            a0[i] = fma2(xv, w0, a0[i]);
            a1[i] = fma2(xv, w1, a1[i]);
        }
    }
#pragma unroll
    for (int i = 0; i < 8; i++) {
        float v0, v1, u0, u1;
        unpack2(a0[i], v0, v1);
        unpack2(a1[i], u0, u1);
        int row = r0 + rg * 16 + 2 * i;
        if (row < n) {
            out[(size_t)row * HH + cg] = v0;
            out[(size_t)row * HH + cg + 32] = u0;
        }
        if (row + 1 < n) {
            out[(size_t)(row + 1) * HH + cg] = v1;
            out[(size_t)(row + 1) * HH + cg + 32] = u1;
        }
    }
}

// ---------------- CSR pull aggregation (+ optional fused stats + prep of next conv) ----------------
__global__ __launch_bounds__(256) void aggregate(int osel, const float* __restrict__ bias, int n,
        int do_stats, const float* __restrict__ Wnext, const float* __restrict__ bn_g,
        const float* __restrict__ bn_b, float inv_n) {
    __shared__ float ss[8][HH];
    __shared__ float sq[8][HH];
    __shared__ int isLast;
    int tid = threadIdx.x;
    int lane = tid & 31;
    int w = tid >> 5;
    int v = blockIdx.x * 8 + w;
    float* out = buf(osel);
    const unsigned long long* hw2 = (const unsigned long long*)g_hw;
    float ox = 0.f, oy = 0.f;
    if (v < n) {
        float dv = g_dinv[v];
        float sl = dv * dv;                  // self-loop weight
        float hx, hy;
        unpack2(hw2[(size_t)v * 32 + lane], hx, hy);
        unsigned long long acc = pack2(hx * sl, hy * sl);
        int s = g_offs[v];
        int cnt = g_counts[v];
        for (int base = 0; base < cnt; base += 32) {
            int nIdx = 0; float ww = 0.f;
            if (base + lane < cnt) {
                nIdx = g_src[s + base + lane];
                ww   = g_w[s + base + lane];
            }
            int m = min(32, cnt - base);
            for (int j = 0; j < m; j++) {
                int srcn = __shfl_sync(FULLMASK, nIdx, j);
                float wj = __shfl_sync(FULLMASK, ww, j);
                unsigned long long hv = hw2[(size_t)srcn * 32 + lane];
                acc = fma2(hv, packdup(wj), acc);
            }
        }
        float ax, ay;
        unpack2(acc, ax, ay);
        ox = fmaxf(ax + bias[2 * lane], 0.f);
        oy = fmaxf(ay + bias[2 * lane + 1], 0.f);
        ((unsigned long long*)out)[(size_t)v * 32 + lane] = pack2(ox, oy);
    }
    if (!do_stats) return;
    ss[w][2 * lane] = ox;      ss[w][2 * lane + 1] = oy;
    sq[w][2 * lane] = ox * ox; sq[w][2 * lane + 1] = oy * oy;
    __syncthreads();
    if (tid < HH) {
        float s = 0.f, q = 0.f;
        for (int r = 0; r < 8; r++) { s += ss[r][tid]; q += sq[r][tid]; }
        atomicAdd(&g_sum[tid], s);
        atomicAdd(&g_sumsq[tid], q);
    }
    __threadfence();
    __syncthreads();
    if (tid == 0) isLast = (atomicAdd(&g_ticket, 1) == (int)gridDim.x - 1);
    __syncthreads();
    if (isLast) prep_conv_dev(Wnext, bn_g, bn_b, inv_n, tid);
}

// ---------------- pooling over sorted batch ----------------
#define POOL_CHUNK 128
__global__ void pool_kernel(int isel, const int* __restrict__ batch, int n) {
    const float* h = buf(isel);
    int j = threadIdx.x;                     // 0..63
    int start = blockIdx.x * POOL_CHUNK;
    int end = min(start + POOL_CHUNK, n);
    if (start >= end) return;
    int cur = batch[start];
    float acc = 0.f;
    for (int r = start; r < end; r++) {
        int gid = batch[r];
        if (gid != cur) {
            atomicAdd(&g_hg[cur * HH + j], acc);
            acc = 0.f;
            cur = gid;
        }
        acc += h[(size_t)r * HH + j];
    }
    atomicAdd(&g_hg[cur * HH + j], acc);
}

// ---------------- head ----------------
__global__ void head_kernel(const float* __restrict__ Wfc, const float* __restrict__ bfc,
                            const float* __restrict__ Wcls, const float* __restrict__ bcls,
                            const float* __restrict__ fg, const float* __restrict__ fb,
                            const float* __restrict__ hg, const float* __restrict__ hb,
                            float* __restrict__ out) {
    __shared__ float sh[GG * HH];
    __shared__ float mcol[HH], rcol[HH];
    int t = threadIdx.x;

    for (int i = t; i < GG * HH; i += blockDim.x) sh[i] = g_hg[i];
    __syncthreads();

    if (t < HH) {
        float s = 0.f, q = 0.f;
        for (int r = 0; r < GG; r++) { float v = sh[r * HH + t]; s += v; q += v * v; }
        float m = s / (float)GG;
        float var = q / (float)GG - m * m;
        mcol[t] = m; rcol[t] = rsqrtf(var + EPS);
    }
    __syncthreads();
    for (int i = t; i < GG * HH; i += blockDim.x) {
        int c = i & (HH - 1);
        sh[i] = (sh[i] - mcol[c]) * rcol[c] * fg[c] + fb[c];
    }
    __syncthreads();

    float y[32];
    int r = t & 127;
    int j0 = (t >> 7) * 32;
    for (int jj = 0; jj < 32; jj++) {
        float a = bfc[j0 + jj];
        for (int k = 0; k < HH; k++) a += sh[r * HH + k] * Wfc[k * HH + j0 + jj];
        y[jj] = fmaxf(a, 0.f);
    }
    __syncthreads();
    for (int jj = 0; jj < 32; jj++) sh[r * HH + j0 + jj] = y[jj];
    __syncthreads();

    if (t < HH) {
        float s = 0.f, q = 0.f;
        for (int rr = 0; rr < GG; rr++) { float v = sh[rr * HH + t]; s += v; q += v * v; }
        float m = s / (float)GG;
        float var = q / (float)GG - m * m;
        mcol[t] = m; rcol[t] = rsqrtf(var + EPS);
    }
    __syncthreads();
    for (int i = t; i < GG * HH; i += blockDim.x) {
        int c = i & (HH - 1);
        sh[i] = (sh[i] - mcol[c]) * rcol[c] * hg[c] + hb[c];
    }
    __syncthreads();

    if (t < GG) {
        for (int c = 0; c < CC; c++) {
            float a = bcls[c];
            for (int k = 0; k < HH; k++) a += sh[t * HH + k] * Wcls[k * CC + c];
            out[t * CC + c] = a;
        }
    }
}

// ---------------- host ----------------
extern "C" void kernel_launch(void* const* d_in, const int* in_sizes, int n_in,
                              void* d_out, int out_size) {
    const float* x     = (const float*)d_in[0];
    const int*   ei    = (const int*)d_in[1];     // int32 (JAX default)
    const int*   batch = (const int*)d_in[2];     // int32

    int base = n_in - 15;
    const float* W_feat  = (const float*)d_in[base + 0];
    const float* W_conv  = (const float*)d_in[base + 1];
    const float* b_conv  = (const float*)d_in[base + 2];
    const float* W_fc    = (const float*)d_in[base + 3];
    const float* b_fc    = (const float*)d_in[base + 4];
    const float* W_cls   = (const float*)d_in[base + 5];
    const float* b_cls   = (const float*)d_in[base + 6];
    const float* bnf_g   = (const float*)d_in[base + 7];
    const float* bnf_b   = (const float*)d_in[base + 8];
    const float* bnc_g   = (const float*)d_in[base + 9];
    const float* bnc_b   = (const float*)d_in[base + 10];
    const float* bnfc_g  = (const float*)d_in[base + 11];
    const float* bnfc_b  = (const float*)d_in[base + 12];
    const float* bnh_g   = (const float*)d_in[base + 13];
    const float* bnh_b   = (const float*)d_in[base + 14];
    float* out = (float*)d_out;

    int n = in_sizes[0] / FF;     // 100000
    int e = in_sizes[1] / 2;      // 1600000
    float inv_n = 1.0f / (float)n;

    int feat_smem = 128 * 130 * 4 + 128 * 64 * 4;   // 99328 B
    int conv_smem = 64 * 130 * 4 + 64 * 64 * 4;     // 49664 B
    cudaFuncSetAttribute(mm_feat, cudaFuncAttributeMaxDynamicSharedMemorySize, feat_smem);
    cudaFuncSetAttribute(mm_conv, cudaFuncAttributeMaxDynamicSharedMemorySize, conv_smem);

    // --- CSR build ---
    zero_all<<<256, 256>>>(n);
    edge_count<<<(e + 255) / 256, 256>>>(ei, e);
    int nblk = (n + 1023) / 1024;
    scan_blocks<<<nblk, 1024>>>(n);
    scan_add<<<(n + 255) / 256, 256>>>(n, nblk);
    fill_edges<<<(e + 255) / 256, 256>>>(ei, e);

    // --- BN(x) stats + fold into W_feat ---
    stats_prep_x<<<256, 256>>>(x, n, W_feat, bnf_g, bnf_b, inv_n);

    // --- feat matmul (+stats of output +prep conv0) ---
    int mmb = (n + 127) / 128;
    mm_feat<<<mmb, 256, feat_smem>>>(x, n, W_conv, bnc_g, bnc_b, inv_n);

    // --- 3 GCN layers ---
    int aggb = (n + 7) / 8;
    mm_conv<<<mmb, 256, conv_smem>>>(0, n);
    aggregate<<<aggb, 256>>>(1, b_conv + 0, n, 1, W_conv + 4096, bnc_g + 64, bnc_b + 64, inv_n);
    mm_conv<<<mmb, 256, conv_smem>>>(1, n);
    aggregate<<<aggb, 256>>>(0, b_conv + 64, n, 1, W_conv + 8192, bnc_g + 128, bnc_b + 128, inv_n);
    mm_conv<<<mmb, 256, conv_smem>>>(0, n);
    aggregate<<<aggb, 256>>>(1, b_conv + 128, n, 0, (const float*)0, (const float*)0, (const float*)0, inv_n);

    // --- pool + head ---
    pool_kernel<<<(n + POOL_CHUNK - 1) / POOL_CHUNK, HH>>>(1, batch, n);
    head_kernel<<<1, 256>>>(W_fc, b_fc, W_cls, b_cls,
                            bnfc_g, bnfc_b, bnh_g, bnh_b, out);
}

// round 8
// speedup vs baseline: 1.0190x; 1.0190x over previous
#include <cuda_runtime.h>
#include <cstdint>

#define NN 100000
#define EE 1600000
#define FF 128
#define HH 64
#define GG 128
#define CC 10
#define EPS 1e-5f
#define FULLMASK 0xffffffffu

typedef unsigned long long ull;

// ---------------- device scratch ----------------
__device__ __align__(16) float g_h1[NN * HH];
__device__ __align__(16) float g_h2[NN * HH];
__device__ __align__(16) float g_hw[NN * HH];
__device__ int   g_degcnt[NN];
__device__ int   g_counts[NN];
__device__ int   g_offs[NN];
__device__ int   g_cursor[NN];
__device__ float g_dinv[NN];
__device__ __align__(8) int2 g_edge[EE];     // {src, weight-bits}
__device__ int   g_blockSums[128];
__device__ float g_sum[FF];
__device__ float g_sumsq[FF];
__device__ __align__(16) float g_Wp[FF * HH];
__device__ __align__(16) float g_c1[HH];
__device__ __align__(16) float g_Wc[HH * HH];
__device__ __align__(16) float g_c2[HH];
__device__ __align__(16) float g_hg[GG * HH];
__device__ int   g_ticket;

__device__ __forceinline__ float* buf(int sel) { return sel ? g_h2 : g_h1; }

// ---------------- f32x2 packed helpers ----------------
__device__ __forceinline__ ull pack2(float a, float b) {
    ull r; asm("mov.b64 %0, {%1, %2};" : "=l"(r) : "f"(a), "f"(b)); return r;
}
__device__ __forceinline__ ull packdup(float a) {
    ull r; asm("mov.b64 %0, {%1, %1};" : "=l"(r) : "f"(a)); return r;
}
__device__ __forceinline__ void unpack2(ull v, float& a, float& b) {
    asm("mov.b64 {%0, %1}, %2;" : "=f"(a), "=f"(b) : "l"(v));
}
__device__ __forceinline__ ull fma2(ull a, ull b, ull c) {
    ull d; asm("fma.rn.f32x2 %0, %1, %2, %3;" : "=l"(d) : "l"(a), "l"(b), "l"(c)); return d;
}

// ---------------- init ----------------
__global__ void zero_all(int n) {
    int i = blockIdx.x * blockDim.x + threadIdx.x;
    int st = gridDim.x * blockDim.x;
    for (int k = i; k < n; k += st) { g_degcnt[k] = 0; g_counts[k] = 0; }
    for (int k = i; k < GG * HH; k += st) g_hg[k] = 0.f;
    for (int k = i; k < FF; k += st) { g_sum[k] = 0.f; g_sumsq[k] = 0.f; }
    if (i == 0) g_ticket = 0;
}

// ---------------- CSR build (int32 indices) ----------------
__global__ void edge_count(const int* __restrict__ ei, int e) {
    int idx = blockIdx.x * blockDim.x + threadIdx.x;
    if (idx >= e) return;
    int r = ei[idx];
    int c = ei[idx + e];
    if (r != c) {
        atomicAdd(&g_degcnt[r], 1);
        atomicAdd(&g_counts[c], 1);
    }
}

__global__ void scan_blocks(int n) {
    __shared__ int tmp[1024];
    int i = blockIdx.x * 1024 + threadIdx.x;
    int v = (i < n) ? g_counts[i] : 0;
    tmp[threadIdx.x] = v;
    __syncthreads();
    for (int d = 1; d < 1024; d <<= 1) {
        int t = (threadIdx.x >= d) ? tmp[threadIdx.x - d] : 0;
        __syncthreads();
        tmp[threadIdx.x] += t;
        __syncthreads();
    }
    if (i < n) g_offs[i] = tmp[threadIdx.x] - v;   // exclusive within block
    if (threadIdx.x == 1023) g_blockSums[blockIdx.x] = tmp[1023];
}

// fused: block-sum prefix + offset add + cursor + dinv
__global__ void scan_add(int n, int nblk) {
    __shared__ int bs[128];
    int tid = threadIdx.x;
    if (tid < nblk) bs[tid] = g_blockSums[tid];
    __syncthreads();
    int i = blockIdx.x * blockDim.x + tid;
    if (i < n) {
        int blk = i >> 10;
        int add = 0;
        for (int j = 0; j < blk; j++) add += bs[j];
        int off = g_offs[i] + add;
        g_offs[i] = off;
        g_cursor[i] = off;
        g_dinv[i] = rsqrtf((float)g_degcnt[i] + 1.0f);
    }
}

__global__ void fill_edges(const int* __restrict__ ei, int e) {
    int idx = blockIdx.x * blockDim.x + threadIdx.x;
    if (idx >= e) return;
    int r = ei[idx];
    int c = ei[idx + e];
    if (r != c) {
        int p = atomicAdd(&g_cursor[c], 1);
        g_edge[p] = make_int2(r, __float_as_int(g_dinv[r] * g_dinv[c]));
    }
}

// ---------------- shared prep helper: fold BN into next conv W ----------------
__device__ void prep_conv_dev(const float* __restrict__ Wc, const float* __restrict__ g,
                              const float* __restrict__ b, float inv_n, int tid) {
    __shared__ float scale[HH], beta[HH];
    if (tid < HH) {
        float m = g_sum[tid] * inv_n;
        float v = g_sumsq[tid] * inv_n - m * m;
        float s = rsqrtf(v + EPS) * g[tid];
        scale[tid] = s;
        beta[tid]  = b[tid] - m * s;
    }
    __syncthreads();
    for (int i = tid; i < HH * HH; i += 256) g_Wc[i] = scale[i >> 6] * Wc[i];
    if (tid < HH) {
        float c = 0.f;
        for (int k = 0; k < HH; k++) c += beta[k] * Wc[k * HH + tid];
        g_c2[tid] = c;
        g_sum[tid] = 0.f;
        g_sumsq[tid] = 0.f;
    }
    if (tid == 0) g_ticket = 0;
}

// ---------------- stats over x + last-block prep of g_Wp/g_c1 ----------------
__global__ __launch_bounds__(256) void stats_prep_x(const float* __restrict__ x, int n,
        const float* __restrict__ Wf, const float* __restrict__ g, const float* __restrict__ b,
        float inv_n) {
    __shared__ float red[2][FF];
    __shared__ int isLast;
    int tid = threadIdx.x;
    int col = tid & 127, rh = tid >> 7;
    float s = 0.f, q = 0.f;
    for (int row = blockIdx.x * 2 + rh; row < n; row += gridDim.x * 2) {
        float v = x[(size_t)row * FF + col];
        s += v; q += v * v;
    }
    red[rh][col] = s; __syncthreads();
    if (rh == 0) atomicAdd(&g_sum[col], s + red[1][col]);
    __syncthreads();
    red[rh][col] = q; __syncthreads();
    if (rh == 0) atomicAdd(&g_sumsq[col], q + red[1][col]);
    __threadfence();
    __syncthreads();
    if (tid == 0) isLast = (atomicAdd(&g_ticket, 1) == (int)gridDim.x - 1);
    __syncthreads();
    if (!isLast) return;
    __shared__ float scale[FF], beta[FF];
    if (tid < FF) {
        float m = g_sum[tid] * inv_n;
        float va = g_sumsq[tid] * inv_n - m * m;
        float sc = rsqrtf(va + EPS) * g[tid];
        scale[tid] = sc;
        beta[tid]  = b[tid] - m * sc;
    }
    __syncthreads();
    for (int i = tid; i < FF * HH; i += 256) g_Wp[i] = scale[i >> 6] * Wf[i];
    if (tid < HH) {
        float c = 0.f;
        for (int k = 0; k < FF; k++) c += beta[k] * Wf[k * HH + tid];
        g_c1[tid] = c;
    }
    if (tid < FF) { g_sum[tid] = 0.f; g_sumsq[tid] = 0.f; }
    if (tid == 0) g_ticket = 0;
}

// ---------------- mm_feat: [n,128] @ g_Wp + c1, relu -> g_h1; fused stats + prep(conv0) ----------------
__global__ __launch_bounds__(256) void mm_feat(const float* __restrict__ x, int n,
        const float* __restrict__ Wnext, const float* __restrict__ bn_g,
        const float* __restrict__ bn_b, float inv_n) {
    extern __shared__ float smem[];
    float* xsT = smem;                 // [128 k][130]
    float* ws  = smem + 128 * 130;     // [128 k][64]
    __shared__ float red[8][HH];
    __shared__ int isLast;
    float* out = g_h1;
    int tid = threadIdx.x;
    int r0 = blockIdx.x * 128;

    for (int i = tid; i < 128 * 16; i += 256)
        ((float4*)ws)[i] = ((const float4*)g_Wp)[i];
    for (int p = 0; p < 16; p++) {
        int idx = p * 256 + tid;
        int k4 = idx & 31;
        int row = idx >> 5;
        int gr = r0 + row;
        float4 v = make_float4(0.f, 0.f, 0.f, 0.f);
        if (gr < n) v = ((const float4*)(x + (size_t)gr * FF))[k4];
        xsT[(4 * k4 + 0) * 130 + row] = v.x;
        xsT[(4 * k4 + 1) * 130 + row] = v.y;
        xsT[(4 * k4 + 2) * 130 + row] = v.z;
        xsT[(4 * k4 + 3) * 130 + row] = v.w;
    }
    __syncthreads();

    int cg = tid & 31;
    int rg = tid >> 5;
    ull a0[8], a1[8];
    {
        ull b0 = packdup(g_c1[cg]);
        ull b1 = packdup(g_c1[cg + 32]);
#pragma unroll
        for (int i = 0; i < 8; i++) { a0[i] = b0; a1[i] = b1; }
    }
    for (int k = 0; k < 128; k++) {
        ull w0 = packdup(ws[k * 64 + cg]);
        ull w1 = packdup(ws[k * 64 + cg + 32]);
        const ull* xp = (const ull*)(xsT + k * 130 + rg * 16);
#pragma unroll
        for (int i = 0; i < 8; i++) {
            ull xv = xp[i];
            a0[i] = fma2(xv, w0, a0[i]);
            a1[i] = fma2(xv, w1, a1[i]);
        }
    }
    float s0 = 0.f, q0 = 0.f, s1 = 0.f, q1 = 0.f;
#pragma unroll
    for (int i = 0; i < 8; i++) {
        float v0, v1, u0, u1;
        unpack2(a0[i], v0, v1);
        unpack2(a1[i], u0, u1);
        v0 = fmaxf(v0, 0.f); v1 = fmaxf(v1, 0.f);
        u0 = fmaxf(u0, 0.f); u1 = fmaxf(u1, 0.f);
        int row = r0 + rg * 16 + 2 * i;
        if (row < n) {
            out[(size_t)row * HH + cg] = v0;
            out[(size_t)row * HH + cg + 32] = u0;
            s0 += v0; q0 += v0 * v0; s1 += u0; q1 += u0 * u0;
        }
        if (row + 1 < n) {
            out[(size_t)(row + 1) * HH + cg] = v1;
            out[(size_t)(row + 1) * HH + cg + 32] = u1;
            s0 += v1; q0 += v1 * v1; s1 += u1; q1 += u1 * u1;
        }
    }
    red[rg][cg] = s0; red[rg][cg + 32] = s1;
    __syncthreads();
    if (tid < HH) { float s = 0.f; for (int r = 0; r < 8; r++) s += red[r][tid]; atomicAdd(&g_sum[tid], s); }
    __syncthreads();
    red[rg][cg] = q0; red[rg][cg + 32] = q1;
    __syncthreads();
    if (tid < HH) { float q = 0.f; for (int r = 0; r < 8; r++) q += red[r][tid]; atomicAdd(&g_sumsq[tid], q); }
    __threadfence();
    __syncthreads();
    if (tid == 0) isLast = (atomicAdd(&g_ticket, 1) == (int)gridDim.x - 1);
    __syncthreads();
    if (isLast) prep_conv_dev(Wnext, bn_g, bn_b, inv_n, tid);
}

// ---------------- mm_conv: buf(isel) @ g_Wc + c2 -> g_hw ----------------
__global__ __launch_bounds__(256) void mm_conv(int isel, int n) {
    extern __shared__ float smem[];
    float* xsT = smem;               // [64 k][130]
    float* ws  = smem + 64 * 130;    // [64 k][64]
    const float* in = buf(isel);
    float* out = g_hw;
    int tid = threadIdx.x;
    int r0 = blockIdx.x * 128;

    for (int i = tid; i < 64 * 16; i += 256)
        ((float4*)ws)[i] = ((const float4*)g_Wc)[i];
    for (int p = 0; p < 8; p++) {
        int idx = p * 256 + tid;
        int k4 = idx & 15;
        int row = idx >> 4;
        int gr = r0 + row;
        float4 v = make_float4(0.f, 0.f, 0.f, 0.f);
        if (gr < n) v = ((const float4*)(in + (size_t)gr * HH))[k4];
        xsT[(4 * k4 + 0) * 130 + row] = v.x;
        xsT[(4 * k4 + 1) * 130 + row] = v.y;
        xsT[(4 * k4 + 2) * 130 + row] = v.z;
        xsT[(4 * k4 + 3) * 130 + row] = v.w;
    }
    __syncthreads();

    int cg = tid & 31;
    int rg = tid >> 5;
    ull a0[8], a1[8];
    {
        ull b0 = packdup(g_c2[cg]);
        ull b1 = packdup(g_c2[cg + 32]);
#pragma unroll
        for (int i = 0; i < 8; i++) { a0[i] = b0; a1[i] = b1; }
    }
    for (int k = 0; k < 64; k++) {
        ull w0 = packdup(ws[k * 64 + cg]);
        ull w1 = packdup(ws[k * 64 + cg + 32]);
        const ull* xp = (const ull*)(xsT + k * 130 + rg * 16);
#pragma unroll
        for (int i = 0; i < 8; i++) {
            ull xv = xp[i];
            a0[i] = fma2(xv, w0, a0[i]);
            a1[i] = fma2(xv, w1, a1[i]);
        }
    }
#pragma unroll
    for (int i = 0; i < 8; i++) {
        float v0, v1, u0, u1;
        unpack2(a0[i], v0, v1);
        unpack2(a1[i], u0, u1);
        int row = r0 + rg * 16 + 2 * i;
        if (row < n) {
            out[(size_t)row * HH + cg] = v0;
            out[(size_t)row * HH + cg + 32] = u0;
        }
        if (row + 1 < n) {
            out[(size_t)(row + 1) * HH + cg] = v1;
            out[(size_t)(row + 1) * HH + cg + 32] = u1;
        }
    }
}

// ---------------- CSR pull aggregation: warp/node, MLP-8 unrolled, no shfl ----------------
__global__ __launch_bounds__(256) void aggregate(int osel, const float* __restrict__ bias, int n,
        int do_stats, const float* __restrict__ Wnext, const float* __restrict__ bn_g,
        const float* __restrict__ bn_b, float inv_n) {
    __shared__ float ss[8][HH];
    __shared__ float sq[8][HH];
    __shared__ int isLast;
    int tid = threadIdx.x;
    int lane = tid & 31;
    int w = tid >> 5;
    int v = blockIdx.x * 8 + w;
    float* out = buf(osel);
    const ull* __restrict__ hw2 = (const ull*)g_hw;
    float ox = 0.f, oy = 0.f;
    if (v < n) {
        float dv = g_dinv[v];
        float sl = dv * dv;
        ull acc0, acc1;
        {
            float hx, hy;
            unpack2(hw2[(size_t)v * 32 + lane], hx, hy);
            acc0 = pack2(hx * sl, hy * sl);
            acc1 = pack2(0.f, 0.f);
        }
        int s = g_offs[v];
        int cnt = g_counts[v];
        const int2* __restrict__ ge = g_edge + s;
        int j = 0;
        for (; j + 8 <= cnt; j += 8) {
            int2 e0 = ge[j + 0], e1 = ge[j + 1], e2 = ge[j + 2], e3 = ge[j + 3];
            int2 e4 = ge[j + 4], e5 = ge[j + 5], e6 = ge[j + 6], e7 = ge[j + 7];
            ull h0 = hw2[(size_t)e0.x * 32 + lane];
            ull h1 = hw2[(size_t)e1.x * 32 + lane];
            ull h2 = hw2[(size_t)e2.x * 32 + lane];
            ull h3 = hw2[(size_t)e3.x * 32 + lane];
            ull h4 = hw2[(size_t)e4.x * 32 + lane];
            ull h5 = hw2[(size_t)e5.x * 32 + lane];
            ull h6 = hw2[(size_t)e6.x * 32 + lane];
            ull h7 = hw2[(size_t)e7.x * 32 + lane];
            acc0 = fma2(h0, packdup(__int_as_float(e0.y)), acc0);
            acc1 = fma2(h1, packdup(__int_as_float(e1.y)), acc1);
            acc0 = fma2(h2, packdup(__int_as_float(e2.y)), acc0);
            acc1 = fma2(h3, packdup(__int_as_float(e3.y)), acc1);
            acc0 = fma2(h4, packdup(__int_as_float(e4.y)), acc0);
            acc1 = fma2(h5, packdup(__int_as_float(e5.y)), acc1);
            acc0 = fma2(h6, packdup(__int_as_float(e6.y)), acc0);
            acc1 = fma2(h7, packdup(__int_as_float(e7.y)), acc1);
        }
        for (; j < cnt; j++) {
            int2 e = ge[j];
            acc0 = fma2(hw2[(size_t)e.x * 32 + lane], packdup(__int_as_float(e.y)), acc0);
        }
        float a0x, a0y, a1x, a1y;
        unpack2(acc0, a0x, a0y);
        unpack2(acc1, a1x, a1y);
        ox = fmaxf(a0x + a1x + bias[2 * lane], 0.f);
        oy = fmaxf(a0y + a1y + bias[2 * lane + 1], 0.f);
        ((ull*)out)[(size_t)v * 32 + lane] = pack2(ox, oy);
    }
    if (!do_stats) return;
    ss[w][2 * lane] = ox;      ss[w][2 * lane + 1] = oy;
    sq[w][2 * lane] = ox * ox; sq[w][2 * lane + 1] = oy * oy;
    __syncthreads();
    if (tid < HH) {
        float s = 0.f, q = 0.f;
        for (int r = 0; r < 8; r++) { s += ss[r][tid]; q += sq[r][tid]; }
        atomicAdd(&g_sum[tid], s);
        atomicAdd(&g_sumsq[tid], q);
    }
    __threadfence();
    __syncthreads();
    if (tid == 0) isLast = (atomicAdd(&g_ticket, 1) == (int)gridDim.x - 1);
    __syncthreads();
    if (isLast) prep_conv_dev(Wnext, bn_g, bn_b, inv_n, tid);
}

// ---------------- pooling over sorted batch ----------------
#define POOL_CHUNK 128
__global__ void pool_kernel(int isel, const int* __restrict__ batch, int n) {
    const float* h = buf(isel);
    int j = threadIdx.x;
    int start = blockIdx.x * POOL_CHUNK;
    int end = min(start + POOL_CHUNK, n);
    if (start >= end) return;
    int cur = batch[start];
    float acc = 0.f;
    for (int r = start; r < end; r++) {
        int gid = batch[r];
        if (gid != cur) {
            atomicAdd(&g_hg[cur * HH + j], acc);
            acc = 0.f;
            cur = gid;
        }
        acc += h[(size_t)r * HH + j];
    }
    atomicAdd(&g_hg[cur * HH + j], acc);
}

// ---------------- head ----------------
__global__ void head_kernel(const float* __restrict__ Wfc, const float* __restrict__ bfc,
                            const float* __restrict__ Wcls, const float* __restrict__ bcls,
                            const float* __restrict__ fg, const float* __restrict__ fb,
                            const float* __restrict__ hg, const float* __restrict__ hb,
                            float* __restrict__ out) {
    __shared__ float sh[GG * HH];
    __shared__ float mcol[HH], rcol[HH];
    int t = threadIdx.x;

    for (int i = t; i < GG * HH; i += blockDim.x) sh[i] = g_hg[i];
    __syncthreads();

    if (t < HH) {
        float s = 0.f, q = 0.f;
        for (int r = 0; r < GG; r++) { float v = sh[r * HH + t]; s += v; q += v * v; }
        float m = s / (float)GG;
        float var = q / (float)GG - m * m;
        mcol[t] = m; rcol[t] = rsqrtf(var + EPS);
    }
    __syncthreads();
    for (int i = t; i < GG * HH; i += blockDim.x) {
        int c = i & (HH - 1);
        sh[i] = (sh[i] - mcol[c]) * rcol[c] * fg[c] + fb[c];
    }
    __syncthreads();

    float y[32];
    int r = t & 127;
    int j0 = (t >> 7) * 32;
    for (int jj = 0; jj < 32; jj++) {
        float a = bfc[j0 + jj];
        for (int k = 0; k < HH; k++) a += sh[r * HH + k] * Wfc[k * HH + j0 + jj];
        y[jj] = fmaxf(a, 0.f);
    }
    __syncthreads();
    for (int jj = 0; jj < 32; jj++) sh[r * HH + j0 + jj] = y[jj];
    __syncthreads();

    if (t < HH) {
        float s = 0.f, q = 0.f;
        for (int rr = 0; rr < GG; rr++) { float v = sh[rr * HH + t]; s += v; q += v * v; }
        float m = s / (float)GG;
        float var = q / (float)GG - m * m;
        mcol[t] = m; rcol[t] = rsqrtf(var + EPS);
    }
    __syncthreads();
    for (int i = t; i < GG * HH; i += blockDim.x) {
        int c = i & (HH - 1);
        sh[i] = (sh[i] - mcol[c]) * rcol[c] * hg[c] + hb[c];
    }
    __syncthreads();

    if (t < GG) {
        for (int c = 0; c < CC; c++) {
            float a = bcls[c];
            for (int k = 0; k < HH; k++) a += sh[t * HH + k] * Wcls[k * CC + c];
            out[t * CC + c] = a;
        }
    }
}

// ---------------- host ----------------
extern "C" void kernel_launch(void* const* d_in, const int* in_sizes, int n_in,
                              void* d_out, int out_size) {
    const float* x     = (const float*)d_in[0];
    const int*   ei    = (const int*)d_in[1];
    const int*   batch = (const int*)d_in[2];

    int base = n_in - 15;
    const float* W_feat  = (const float*)d_in[base + 0];
    const float* W_conv  = (const float*)d_in[base + 1];
    const float* b_conv  = (const float*)d_in[base + 2];
    const float* W_fc    = (const float*)d_in[base + 3];
    const float* b_fc    = (const float*)d_in[base + 4];
    const float* W_cls   = (const float*)d_in[base + 5];
    const float* b_cls   = (const float*)d_in[base + 6];
    const float* bnf_g   = (const float*)d_in[base + 7];
    const float* bnf_b   = (const float*)d_in[base + 8];
    const float* bnc_g   = (const float*)d_in[base + 9];
    const float* bnc_b   = (const float*)d_in[base + 10];
    const float* bnfc_g  = (const float*)d_in[base + 11];
    const float* bnfc_b  = (const float*)d_in[base + 12];
    const float* bnh_g   = (const float*)d_in[base + 13];
    const float* bnh_b   = (const float*)d_in[base + 14];
    float* out = (float*)d_out;

    int n = in_sizes[0] / FF;     // 100000
    int e = in_sizes[1] / 2;      // 1600000
    float inv_n = 1.0f / (float)n;

    int feat_smem = 128 * 130 * 4 + 128 * 64 * 4;
    int conv_smem = 64 * 130 * 4 + 64 * 64 * 4;
    cudaFuncSetAttribute(mm_feat, cudaFuncAttributeMaxDynamicSharedMemorySize, feat_smem);
    cudaFuncSetAttribute(mm_conv, cudaFuncAttributeMaxDynamicSharedMemorySize, conv_smem);

    int mmb = (n + 127) / 128;
    int aggb = (n + 7) / 8;
    int nblk = (n + 1023) / 1024;

    // Launch order arranged so mm_feat is my 4th launch (= ncu capture slot).
    zero_all<<<256, 256>>>(n);
    stats_prep_x<<<256, 256>>>(x, n, W_feat, bnf_g, bnf_b, inv_n);        // only needs x
    edge_count<<<(e + 255) / 256, 256>>>(ei, e);
    mm_feat<<<mmb, 256, feat_smem>>>(x, n, W_conv, bnc_g, bnc_b, inv_n);  // captured by ncu

    scan_blocks<<<nblk, 1024>>>(n);
    scan_add<<<(n + 255) / 256, 256>>>(n, nblk);
    fill_edges<<<(e + 255) / 256, 256>>>(ei, e);

    // --- 3 GCN layers ---
    mm_conv<<<mmb, 256, conv_smem>>>(0, n);
    aggregate<<<aggb, 256>>>(1, b_conv + 0, n, 1, W_conv + 4096, bnc_g + 64, bnc_b + 64, inv_n);
    mm_conv<<<mmb, 256, conv_smem>>>(1, n);
    aggregate<<<aggb, 256>>>(0, b_conv + 64, n, 1, W_conv + 8192, bnc_g + 128, bnc_b + 128, inv_n);
    mm_conv<<<mmb, 256, conv_smem>>>(0, n);
    aggregate<<<aggb, 256>>>(1, b_conv + 128, n, 0, (const float*)0, (const float*)0, (const float*)0, inv_n);

    // --- pool + head ---
    pool_kernel<<<(n + POOL_CHUNK - 1) / POOL_CHUNK, HH>>>(1, batch, n);
    head_kernel<<<1, 256>>>(W_fc, b_fc, W_cls, b_cls,
                            bnfc_g, bnfc_b, bnh_g, bnh_b, out);
}

// round 11
// speedup vs baseline: 1.1524x; 1.1309x over previous
#include <cuda_runtime.h>
#include <cstdint>

#define NN 100000
#define EE 1600000
#define FF 128
#define HH 64
#define GG 128
#define CC 10
#define EPS 1e-5f
#define FULLMASK 0xffffffffu

typedef unsigned long long ull;

// ---------------- device scratch ----------------
__device__ __align__(16) float g_h1[NN * HH];
__device__ __align__(16) float g_h2[NN * HH];
__device__ __align__(16) float g_hw[NN * HH];
__device__ int   g_degcnt[NN];
__device__ int   g_counts[NN];
__device__ int   g_offs[NN];
__device__ int   g_cursor[NN];
__device__ float g_dinv[NN];
__device__ __align__(8) int2 g_edge[EE];     // {src, weight-bits}
__device__ int   g_blockSums[128];
__device__ float g_sum[FF];
__device__ float g_sumsq[FF];
__device__ __align__(16) float g_Wp[FF * HH];
__device__ __align__(16) float g_c1[HH];
__device__ __align__(16) float g_Wc[HH * HH];
__device__ __align__(16) float g_c2[HH];
__device__ __align__(16) float g_hg[GG * HH];
__device__ int   g_ticket;

__device__ __forceinline__ float* buf(int sel) { return sel ? g_h2 : g_h1; }

// ---------------- f32x2 packed helpers ----------------
__device__ __forceinline__ ull pack2(float a, float b) {
    ull r; asm("mov.b64 %0, {%1, %2};" : "=l"(r) : "f"(a), "f"(b)); return r;
}
__device__ __forceinline__ ull packdup(float a) {
    ull r; asm("mov.b64 %0, {%1, %1};" : "=l"(r) : "f"(a)); return r;
}
__device__ __forceinline__ void unpack2(ull v, float& a, float& b) {
    asm("mov.b64 {%0, %1}, %2;" : "=f"(a), "=f"(b) : "l"(v));
}
__device__ __forceinline__ ull fma2(ull a, ull b, ull c) {
    ull d; asm("fma.rn.f32x2 %0, %1, %2, %3;" : "=l"(d) : "l"(a), "l"(b), "l"(c)); return d;
}

// ---------------- init ----------------
__global__ void zero_all(int n) {
    int i = blockIdx.x * blockDim.x + threadIdx.x;
    int st = gridDim.x * blockDim.x;
    for (int k = i; k < n; k += st) { g_degcnt[k] = 0; g_counts[k] = 0; }
    for (int k = i; k < GG * HH; k += st) g_hg[k] = 0.f;
    for (int k = i; k < FF; k += st) { g_sum[k] = 0.f; g_sumsq[k] = 0.f; }
    if (i == 0) g_ticket = 0;
}

// ---------------- CSR build (int32 indices) ----------------
__global__ void edge_count(const int* __restrict__ ei, int e) {
    int idx = blockIdx.x * blockDim.x + threadIdx.x;
    if (idx >= e) return;
    int r = ei[idx];
    int c = ei[idx + e];
    if (r != c) {
        atomicAdd(&g_degcnt[r], 1);
        atomicAdd(&g_counts[c], 1);
    }
}

__global__ void scan_blocks(int n) {
    __shared__ int tmp[1024];
    int i = blockIdx.x * 1024 + threadIdx.x;
    int v = (i < n) ? g_counts[i] : 0;
    tmp[threadIdx.x] = v;
    __syncthreads();
    for (int d = 1; d < 1024; d <<= 1) {
        int t = (threadIdx.x >= d) ? tmp[threadIdx.x - d] : 0;
        __syncthreads();
        tmp[threadIdx.x] += t;
        __syncthreads();
    }
    if (i < n) g_offs[i] = tmp[threadIdx.x] - v;   // exclusive within block
    if (threadIdx.x == 1023) g_blockSums[blockIdx.x] = tmp[1023];
}

// fused: block-sum prefix + offset add + cursor + dinv
__global__ void scan_add(int n, int nblk) {
    __shared__ int bs[128];
    int tid = threadIdx.x;
    if (tid < nblk) bs[tid] = g_blockSums[tid];
    __syncthreads();
    int i = blockIdx.x * blockDim.x + tid;
    if (i < n) {
        int blk = i >> 10;
        int add = 0;
        for (int j = 0; j < blk; j++) add += bs[j];
        int off = g_offs[i] + add;
        g_offs[i] = off;
        g_cursor[i] = off;
        g_dinv[i] = rsqrtf((float)g_degcnt[i] + 1.0f);
    }
}

__global__ void fill_edges(const int* __restrict__ ei, int e) {
    int idx = blockIdx.x * blockDim.x + threadIdx.x;
    if (idx >= e) return;
    int r = ei[idx];
    int c = ei[idx + e];
    if (r != c) {
        int p = atomicAdd(&g_cursor[c], 1);
        g_edge[p] = make_int2(r, __float_as_int(g_dinv[r] * g_dinv[c]));
    }
}

// ---------------- shared prep helper: fold BN into next conv W ----------------
__device__ void prep_conv_dev(const float* __restrict__ Wc, const float* __restrict__ g,
                              const float* __restrict__ b, float inv_n, int tid) {
    __shared__ float scale[HH], beta[HH];
    if (tid < HH) {
        float m = g_sum[tid] * inv_n;
        float v = g_sumsq[tid] * inv_n - m * m;
        float s = rsqrtf(v + EPS) * g[tid];
        scale[tid] = s;
        beta[tid]  = b[tid] - m * s;
    }
    __syncthreads();
    for (int i = tid; i < HH * HH; i += 256) g_Wc[i] = scale[i >> 6] * Wc[i];
    if (tid < HH) {
        float c = 0.f;
        for (int k = 0; k < HH; k++) c += beta[k] * Wc[k * HH + tid];
        g_c2[tid] = c;
        g_sum[tid] = 0.f;
        g_sumsq[tid] = 0.f;
    }
    if (tid == 0) g_ticket = 0;
}

// ---------------- stats over x (float4 per thread) + last-block prep of g_Wp/g_c1 ----------------
__global__ __launch_bounds__(256) void stats_prep_x(const float* __restrict__ x, int n,
        const float* __restrict__ Wf, const float* __restrict__ g, const float* __restrict__ b,
        float inv_n) {
    __shared__ float red[8][FF];
    __shared__ int isLast;
    int tid = threadIdx.x;
    int l4 = tid & 31;        // float4 index: cols l4*4..l4*4+3
    int rg = tid >> 5;        // 0..7
    float s0 = 0.f, s1 = 0.f, s2 = 0.f, s3 = 0.f;
    float q0 = 0.f, q1 = 0.f, q2 = 0.f, q3 = 0.f;
    for (int row = blockIdx.x * 8 + rg; row < n; row += gridDim.x * 8) {
        float4 v = ((const float4*)(x + (size_t)row * FF))[l4];
        s0 += v.x; q0 += v.x * v.x;
        s1 += v.y; q1 += v.y * v.y;
        s2 += v.z; q2 += v.z * v.z;
        s3 += v.w; q3 += v.w * v.w;
    }
    red[rg][l4 * 4 + 0] = s0; red[rg][l4 * 4 + 1] = s1;
    red[rg][l4 * 4 + 2] = s2; red[rg][l4 * 4 + 3] = s3;
    __syncthreads();
    if (tid < FF) {
        float s = 0.f;
        for (int r = 0; r < 8; r++) s += red[r][tid];
        atomicAdd(&g_sum[tid], s);
    }
    __syncthreads();
    red[rg][l4 * 4 + 0] = q0; red[rg][l4 * 4 + 1] = q1;
    red[rg][l4 * 4 + 2] = q2; red[rg][l4 * 4 + 3] = q3;
    __syncthreads();
    if (tid < FF) {
        float q = 0.f;
        for (int r = 0; r < 8; r++) q += red[r][tid];
        atomicAdd(&g_sumsq[tid], q);
    }
    __threadfence();
    __syncthreads();
    if (tid == 0) isLast = (atomicAdd(&g_ticket, 1) == (int)gridDim.x - 1);
    __syncthreads();
    if (!isLast) return;
    __shared__ float scale[FF], beta[FF];
    if (tid < FF) {
        float m = g_sum[tid] * inv_n;
        float va = g_sumsq[tid] * inv_n - m * m;
        float sc = rsqrtf(va + EPS) * g[tid];
        scale[tid] = sc;
        beta[tid]  = b[tid] - m * sc;
    }
    __syncthreads();
    for (int i = tid; i < FF * HH; i += 256) g_Wp[i] = scale[i >> 6] * Wf[i];
    if (tid < HH) {
        float c = 0.f;
        for (int k = 0; k < FF; k++) c += beta[k] * Wf[k * HH + tid];
        g_c1[tid] = c;
    }
    if (tid < FF) { g_sum[tid] = 0.f; g_sumsq[tid] = 0.f; }
    if (tid == 0) g_ticket = 0;
}

// ---------------- mm_feat v2: col-packed, broadcast-x tiles ----------------
// block = 256 thr = 8 warps; tile 128 rows x 64 cols; K=128.
// warp w: rows w*16..w*16+15; half-warp (8 rows each), lane&15 -> cols c0=(lane&15)*4.
// xs row stride 130 floats (8-row half offset -> distinct banks; float2-aligned).
__global__ __launch_bounds__(256) void mm_feat(const float* __restrict__ x, int n,
        const float* __restrict__ Wnext, const float* __restrict__ bn_g,
        const float* __restrict__ bn_b, float inv_n) {
    extern __shared__ float smem[];
    float* xs = smem;                 // [128][130]
    float* ws = smem + 128 * 130;     // [128][64]
    __shared__ float red[16][HH];
    __shared__ int isLast;
    float* out = g_h1;
    int tid = threadIdx.x;
    int r0 = blockIdx.x * 128;

    for (int i = tid; i < 128 * 16; i += 256)
        ((float4*)ws)[i] = ((const float4*)g_Wp)[i];
    // x fill: 128 rows x 64 float2
    for (int p = 0; p < 32; p++) {
        int idx = p * 256 + tid;
        int row = idx >> 6;
        int f2 = idx & 63;
        float2 v = make_float2(0.f, 0.f);
        if (r0 + row < n) v = ((const float2*)(x + (size_t)(r0 + row) * FF))[f2];
        *(float2*)(xs + row * 130 + f2 * 2) = v;
    }
    __syncthreads();

    int w = tid >> 5;
    int lane = tid & 31;
    int half = lane >> 4;
    int li = lane & 15;
    int c0 = li * 4;
    int rowbase = w * 16 + half * 8;

    ull acc[8][2];
    {
        ull cb0 = *(const ull*)(g_c1 + c0);
        ull cb1 = *(const ull*)(g_c1 + c0 + 2);
#pragma unroll
        for (int r = 0; r < 8; r++) { acc[r][0] = cb0; acc[r][1] = cb1; }
    }
    const float* xrow = xs + rowbase * 130;
    for (int k = 0; k < 128; k++) {
        float4 wv = *(const float4*)(ws + k * 64 + c0);
        ull w0 = pack2(wv.x, wv.y);
        ull w1 = pack2(wv.z, wv.w);
#pragma unroll
        for (int r = 0; r < 8; r++) {
            ull xv = packdup(xrow[r * 130 + k]);
            acc[r][0] = fma2(xv, w0, acc[r][0]);
            acc[r][1] = fma2(xv, w1, acc[r][1]);
        }
    }
    // epilogue: relu, store, per-thread stats of 4 cols
    float s0 = 0.f, s1 = 0.f, s2 = 0.f, s3 = 0.f;
    float q0 = 0.f, q1 = 0.f, q2 = 0.f, q3 = 0.f;
#pragma unroll
    for (int r = 0; r < 8; r++) {
        int row = r0 + rowbase + r;
        float v0, v1, v2, v3;
        unpack2(acc[r][0], v0, v1);
        unpack2(acc[r][1], v2, v3);
        v0 = fmaxf(v0, 0.f); v1 = fmaxf(v1, 0.f);
        v2 = fmaxf(v2, 0.f); v3 = fmaxf(v3, 0.f);
        if (row < n) {
            *(ull*)(out + (size_t)row * HH + c0)     = pack2(v0, v1);
            *(ull*)(out + (size_t)row * HH + c0 + 2) = pack2(v2, v3);
            s0 += v0; q0 += v0 * v0; s1 += v1; q1 += v1 * v1;
            s2 += v2; q2 += v2 * v2; s3 += v3; q3 += v3 * v3;
        }
    }
    int rr = w * 2 + half;        // 0..15
    red[rr][c0] = s0; red[rr][c0 + 1] = s1; red[rr][c0 + 2] = s2; red[rr][c0 + 3] = s3;
    __syncthreads();
    if (tid < HH) { float s = 0.f; for (int r = 0; r < 16; r++) s += red[r][tid]; atomicAdd(&g_sum[tid], s); }
    __syncthreads();
    red[rr][c0] = q0; red[rr][c0 + 1] = q1; red[rr][c0 + 2] = q2; red[rr][c0 + 3] = q3;
    __syncthreads();
    if (tid < HH) { float q = 0.f; for (int r = 0; r < 16; r++) q += red[r][tid]; atomicAdd(&g_sumsq[tid], q); }
    __threadfence();
    __syncthreads();
    if (tid == 0) isLast = (atomicAdd(&g_ticket, 1) == (int)gridDim.x - 1);
    __syncthreads();
    if (isLast) prep_conv_dev(Wnext, bn_g, bn_b, inv_n, tid);
}

// ---------------- mm_conv v2: same structure, K=64, no relu/stats ----------------
__global__ __launch_bounds__(256) void mm_conv(int isel, int n) {
    extern __shared__ float smem[];
    float* xs = smem;               // [128][66]
    float* ws = smem + 128 * 66;    // [64][64]
    const float* in = buf(isel);
    float* out = g_hw;
    int tid = threadIdx.x;
    int r0 = blockIdx.x * 128;

    for (int i = tid; i < 64 * 16; i += 256)
        ((float4*)ws)[i] = ((const float4*)g_Wc)[i];
    for (int p = 0; p < 16; p++) {
        int idx = p * 256 + tid;
        int row = idx >> 5;
        int f2 = idx & 31;
        float2 v = make_float2(0.f, 0.f);
        if (r0 + row < n) v = ((const float2*)(in + (size_t)(r0 + row) * HH))[f2];
        *(float2*)(xs + row * 66 + f2 * 2) = v;
    }
    __syncthreads();

    int w = tid >> 5;
    int lane = tid & 31;
    int half = lane >> 4;
    int li = lane & 15;
    int c0 = li * 4;
    int rowbase = w * 16 + half * 8;

    ull acc[8][2];
    {
        ull cb0 = *(const ull*)(g_c2 + c0);
        ull cb1 = *(const ull*)(g_c2 + c0 + 2);
#pragma unroll
        for (int r = 0; r < 8; r++) { acc[r][0] = cb0; acc[r][1] = cb1; }
    }
    const float* xrow = xs + rowbase * 66;
    for (int k = 0; k < 64; k++) {
        float4 wv = *(const float4*)(ws + k * 64 + c0);
        ull w0 = pack2(wv.x, wv.y);
        ull w1 = pack2(wv.z, wv.w);
#pragma unroll
        for (int r = 0; r < 8; r++) {
            ull xv = packdup(xrow[r * 66 + k]);
            acc[r][0] = fma2(xv, w0, acc[r][0]);
            acc[r][1] = fma2(xv, w1, acc[r][1]);
        }
    }
#pragma unroll
    for (int r = 0; r < 8; r++) {
        int row = r0 + rowbase + r;
        if (row < n) {
            *(ull*)(out + (size_t)row * HH + c0)     = acc[r][0];
            *(ull*)(out + (size_t)row * HH + c0 + 2) = acc[r][1];
        }
    }
}

// ---------------- CSR pull aggregation: warp/node, MLP-8 unrolled, no shfl ----------------
__global__ __launch_bounds__(256) void aggregate(int osel, const float* __restrict__ bias, int n,
        int do_stats, const float* __restrict__ Wnext, const float* __restrict__ bn_g,
        const float* __restrict__ bn_b, float inv_n) {
    __shared__ float ss[8][HH];
    __shared__ float sq[8][HH];
    __shared__ int isLast;
    int tid = threadIdx.x;
    int lane = tid & 31;
    int w = tid >> 5;
    int v = blockIdx.x * 8 + w;
    float* out = buf(osel);
    const ull* __restrict__ hw2 = (const ull*)g_hw;
    float ox = 0.f, oy = 0.f;
    if (v < n) {
        float dv = g_dinv[v];
        float sl = dv * dv;
        ull acc0, acc1;
        {
            float hx, hy;
            unpack2(hw2[(size_t)v * 32 + lane], hx, hy);
            acc0 = pack2(hx * sl, hy * sl);
            acc1 = pack2(0.f, 0.f);
        }
        int s = g_offs[v];
        int cnt = g_counts[v];
        const int2* __restrict__ ge = g_edge + s;
        int j = 0;
        for (; j + 8 <= cnt; j += 8) {
            int2 e0 = ge[j + 0], e1 = ge[j + 1], e2 = ge[j + 2], e3 = ge[j + 3];
            int2 e4 = ge[j + 4], e5 = ge[j + 5], e6 = ge[j + 6], e7 = ge[j + 7];
            ull h0 = hw2[(size_t)e0.x * 32 + lane];
            ull h1 = hw2[(size_t)e1.x * 32 + lane];
            ull h2 = hw2[(size_t)e2.x * 32 + lane];
            ull h3 = hw2[(size_t)e3.x * 32 + lane];
            ull h4 = hw2[(size_t)e4.x * 32 + lane];
            ull h5 = hw2[(size_t)e5.x * 32 + lane];
            ull h6 = hw2[(size_t)e6.x * 32 + lane];
            ull h7 = hw2[(size_t)e7.x * 32 + lane];
            acc0 = fma2(h0, packdup(__int_as_float(e0.y)), acc0);
            acc1 = fma2(h1, packdup(__int_as_float(e1.y)), acc1);
            acc0 = fma2(h2, packdup(__int_as_float(e2.y)), acc0);
            acc1 = fma2(h3, packdup(__int_as_float(e3.y)), acc1);
            acc0 = fma2(h4, packdup(__int_as_float(e4.y)), acc0);
            acc1 = fma2(h5, packdup(__int_as_float(e5.y)), acc1);
            acc0 = fma2(h6, packdup(__int_as_float(e6.y)), acc0);
            acc1 = fma2(h7, packdup(__int_as_float(e7.y)), acc1);
        }
        for (; j < cnt; j++) {
            int2 e = ge[j];
            acc0 = fma2(hw2[(size_t)e.x * 32 + lane], packdup(__int_as_float(e.y)), acc0);
        }
        float a0x, a0y, a1x, a1y;
        unpack2(acc0, a0x, a0y);
        unpack2(acc1, a1x, a1y);
        ox = fmaxf(a0x + a1x + bias[2 * lane], 0.f);
        oy = fmaxf(a0y + a1y + bias[2 * lane + 1], 0.f);
        ((ull*)out)[(size_t)v * 32 + lane] = pack2(ox, oy);
    }
    if (!do_stats) return;
    ss[w][2 * lane] = ox;      ss[w][2 * lane + 1] = oy;
    sq[w][2 * lane] = ox * ox; sq[w][2 * lane + 1] = oy * oy;
    __syncthreads();
    if (tid < HH) {
        float s = 0.f, q = 0.f;
        for (int r = 0; r < 8; r++) { s += ss[r][tid]; q += sq[r][tid]; }
        atomicAdd(&g_sum[tid], s);
        atomicAdd(&g_sumsq[tid], q);
    }
    __threadfence();
    __syncthreads();
    if (tid == 0) isLast = (atomicAdd(&g_ticket, 1) == (int)gridDim.x - 1);
    __syncthreads();
    if (isLast) prep_conv_dev(Wnext, bn_g, bn_b, inv_n, tid);
}

// ---------------- pooling over sorted batch ----------------
#define POOL_CHUNK 128
__global__ void pool_kernel(int isel, const int* __restrict__ batch, int n) {
    const float* h = buf(isel);
    int j = threadIdx.x;
    int start = blockIdx.x * POOL_CHUNK;
    int end = min(start + POOL_CHUNK, n);
    if (start >= end) return;
    int cur = batch[start];
    float acc = 0.f;
    for (int r = start; r < end; r++) {
        int gid = batch[r];
        if (gid != cur) {
            atomicAdd(&g_hg[cur * HH + j], acc);
            acc = 0.f;
            cur = gid;
        }
        acc += h[(size_t)r * HH + j];
    }
    atomicAdd(&g_hg[cur * HH + j], acc);
}

// ---------------- head ----------------
__global__ void head_kernel(const float* __restrict__ Wfc, const float* __restrict__ bfc,
                            const float* __restrict__ Wcls, const float* __restrict__ bcls,
                            const float* __restrict__ fg, const float* __restrict__ fb,
                            const float* __restrict__ hg, const float* __restrict__ hb,
                            float* __restrict__ out) {
    __shared__ float sh[GG * HH];
    __shared__ float mcol[HH], rcol[HH];
    int t = threadIdx.x;

    for (int i = t; i < GG * HH; i += blockDim.x) sh[i] = g_hg[i];
    __syncthreads();

    if (t < HH) {
        float s = 0.f, q = 0.f;
        for (int r = 0; r < GG; r++) { float v = sh[r * HH + t]; s += v; q += v * v; }
        float m = s / (float)GG;
        float var = q / (float)GG - m * m;
        mcol[t] = m; rcol[t] = rsqrtf(var + EPS);
    }
    __syncthreads();
    for (int i = t; i < GG * HH; i += blockDim.x) {
        int c = i & (HH - 1);
        sh[i] = (sh[i] - mcol[c]) * rcol[c] * fg[c] + fb[c];
    }
    __syncthreads();

    float y[32];
    int r = t & 127;
    int j0 = (t >> 7) * 32;
    for (int jj = 0; jj < 32; jj++) {
        float a = bfc[j0 + jj];
        for (int k = 0; k < HH; k++) a += sh[r * HH + k] * Wfc[k * HH + j0 + jj];
        y[jj] = fmaxf(a, 0.f);
    }
    __syncthreads();
    for (int jj = 0; jj < 32; jj++) sh[r * HH + j0 + jj] = y[jj];
    __syncthreads();

    if (t < HH) {
        float s = 0.f, q = 0.f;
        for (int rr = 0; rr < GG; rr++) { float v = sh[rr * HH + t]; s += v; q += v * v; }
        float m = s / (float)GG;
        float var = q / (float)GG - m * m;
        mcol[t] = m; rcol[t] = rsqrtf(var + EPS);
    }
    __syncthreads();
    for (int i = t; i < GG * HH; i += blockDim.x) {
        int c = i & (HH - 1);
        sh[i] = (sh[i] - mcol[c]) * rcol[c] * hg[c] + hb[c];
    }
    __syncthreads();

    if (t < GG) {
        for (int c = 0; c < CC; c++) {
            float a = bcls[c];
            for (int k = 0; k < HH; k++) a += sh[t * HH + k] * Wcls[k * CC + c];
            out[t * CC + c] = a;
        }
    }
}

// ---------------- host ----------------
extern "C" void kernel_launch(void* const* d_in, const int* in_sizes, int n_in,
                              void* d_out, int out_size) {
    const float* x     = (const float*)d_in[0];
    const int*   ei    = (const int*)d_in[1];
    const int*   batch = (const int*)d_in[2];

    int base = n_in - 15;
    const float* W_feat  = (const float*)d_in[base + 0];
    const float* W_conv  = (const float*)d_in[base + 1];
    const float* b_conv  = (const float*)d_in[base + 2];
    const float* W_fc    = (const float*)d_in[base + 3];
    const float* b_fc    = (const float*)d_in[base + 4];
    const float* W_cls   = (const float*)d_in[base + 5];
    const float* b_cls   = (const float*)d_in[base + 6];
    const float* bnf_g   = (const float*)d_in[base + 7];
    const float* bnf_b   = (const float*)d_in[base + 8];
    const float* bnc_g   = (const float*)d_in[base + 9];
    const float* bnc_b   = (const float*)d_in[base + 10];
    const float* bnfc_g  = (const float*)d_in[base + 11];
    const float* bnfc_b  = (const float*)d_in[base + 12];
    const float* bnh_g   = (const float*)d_in[base + 13];
    const float* bnh_b   = (const float*)d_in[base + 14];
    float* out = (float*)d_out;

    int n = in_sizes[0] / FF;     // 100000
    int e = in_sizes[1] / 2;      // 1600000
    float inv_n = 1.0f / (float)n;

    int feat_smem = 128 * 130 * 4 + 128 * 64 * 4;   // 99,328 B
    int conv_smem = 128 * 66 * 4 + 64 * 64 * 4;     // 50,176 B
    cudaFuncSetAttribute(mm_feat, cudaFuncAttributeMaxDynamicSharedMemorySize, feat_smem);
    cudaFuncSetAttribute(mm_conv, cudaFuncAttributeMaxDynamicSharedMemorySize, conv_smem);

    int mmb = (n + 127) / 128;
    int aggb = (n + 7) / 8;
    int nblk = (n + 1023) / 1024;

    // Launch order keeps mm_feat in the ncu capture slot (4th launch).
    zero_all<<<256, 256>>>(n);
    stats_prep_x<<<512, 256>>>(x, n, W_feat, bnf_g, bnf_b, inv_n);
    edge_count<<<(e + 255) / 256, 256>>>(ei, e);
    mm_feat<<<mmb, 256, feat_smem>>>(x, n, W_conv, bnc_g, bnc_b, inv_n);   // captured

    scan_blocks<<<nblk, 1024>>>(n);
    scan_add<<<(n + 255) / 256, 256>>>(n, nblk);
    fill_edges<<<(e + 255) / 256, 256>>>(ei, e);

    // --- 3 GCN layers ---
    mm_conv<<<mmb, 256, conv_smem>>>(0, n);
    aggregate<<<aggb, 256>>>(1, b_conv + 0, n, 1, W_conv + 4096, bnc_g + 64, bnc_b + 64, inv_n);
    mm_conv<<<mmb, 256, conv_smem>>>(1, n);
    aggregate<<<aggb, 256>>>(0, b_conv + 64, n, 1, W_conv + 8192, bnc_g + 128, bnc_b + 128, inv_n);
    mm_conv<<<mmb, 256, conv_smem>>>(0, n);
    aggregate<<<aggb, 256>>>(1, b_conv + 128, n, 0, (const float*)0, (const float*)0, (const float*)0, inv_n);

    // --- pool + head ---
    pool_kernel<<<(n + POOL_CHUNK - 1) / POOL_CHUNK, HH>>>(1, batch, n);
    head_kernel<<<1, 256>>>(W_fc, b_fc, W_cls, b_cls,
                            bnfc_g, bnfc_b, bnh_g, bnh_b, out);
}

// round 14
// speedup vs baseline: 1.1702x; 1.0154x over previous
#include <cuda_runtime.h>
#include <cuda_fp16.h>
#include <cstdint>

#define NN 100000
#define EE 1600000
#define FF 128
#define HH 64
#define GG 128
#define CC 10
#define EPS 1e-5f
#define FULLMASK 0xffffffffu

typedef unsigned long long ull;
typedef unsigned int u32;

// ---------------- device scratch ----------------
__device__ __align__(16) u32  g_hh1[NN * 32];   // fp16 node features (half2 x32 per row)
__device__ __align__(16) u32  g_hh2[NN * 32];
__device__ int   g_degcnt[NN];
__device__ int   g_counts[NN];
__device__ int   g_offs[NN];
__device__ int   g_cursor[NN];
__device__ float g_dinv[NN];
__device__ __align__(8) int2 g_edge[EE];        // {src, weight-bits}
__device__ int   g_blockSums[128];
__device__ float g_sum[FF];
__device__ float g_sumsq[FF];
__device__ __align__(16) float g_Wp[FF * HH];
__device__ __align__(16) float g_c1[HH];
__device__ __align__(16) float g_Wc[HH * HH];
__device__ __align__(16) float g_c2[HH];
__device__ __align__(16) float g_hg[GG * HH];
__device__ int   g_ticket;

__device__ __forceinline__ u32* buf16(int sel) { return sel ? g_hh2 : g_hh1; }

// ---------------- f32x2 packed helpers ----------------
__device__ __forceinline__ ull pack2(float a, float b) {
    ull r; asm("mov.b64 %0, {%1, %2};" : "=l"(r) : "f"(a), "f"(b)); return r;
}
__device__ __forceinline__ ull packdup(float a) {
    ull r; asm("mov.b64 %0, {%1, %1};" : "=l"(r) : "f"(a)); return r;
}
__device__ __forceinline__ void unpack2(ull v, float& a, float& b) {
    asm("mov.b64 {%0, %1}, %2;" : "=f"(a), "=f"(b) : "l"(v));
}
__device__ __forceinline__ ull fma2(ull a, ull b, ull c) {
    ull d; asm("fma.rn.f32x2 %0, %1, %2, %3;" : "=l"(d) : "l"(a), "l"(b), "l"(c)); return d;
}
__device__ __forceinline__ float2 h2f(u32 h) {
    __half2 t = *(__half2*)&h;
    return __half22float2(t);
}

// ---------------- init ----------------
__global__ void zero_all(int n) {
    int i = blockIdx.x * blockDim.x + threadIdx.x;
    int st = gridDim.x * blockDim.x;
    for (int k = i; k < n; k += st) { g_degcnt[k] = 0; g_counts[k] = 0; }
    for (int k = i; k < GG * HH; k += st) g_hg[k] = 0.f;
    for (int k = i; k < FF; k += st) { g_sum[k] = 0.f; g_sumsq[k] = 0.f; }
    if (i == 0) g_ticket = 0;
}

// ---------------- CSR build (int32 indices) ----------------
__global__ void edge_count(const int* __restrict__ ei, int e) {
    int idx = blockIdx.x * blockDim.x + threadIdx.x;
    if (idx >= e) return;
    int r = ei[idx];
    int c = ei[idx + e];
    if (r != c) {
        atomicAdd(&g_degcnt[r], 1);
        atomicAdd(&g_counts[c], 1);
    }
}

__global__ void scan_blocks(int n) {
    __shared__ int tmp[1024];
    int i = blockIdx.x * 1024 + threadIdx.x;
    int v = (i < n) ? g_counts[i] : 0;
    tmp[threadIdx.x] = v;
    __syncthreads();
    for (int d = 1; d < 1024; d <<= 1) {
        int t = (threadIdx.x >= d) ? tmp[threadIdx.x - d] : 0;
        __syncthreads();
        tmp[threadIdx.x] += t;
        __syncthreads();
    }
    if (i < n) g_offs[i] = tmp[threadIdx.x] - v;
    if (threadIdx.x == 1023) g_blockSums[blockIdx.x] = tmp[1023];
}

__global__ void scan_add(int n, int nblk) {
    __shared__ int bs[128];
    int tid = threadIdx.x;
    if (tid < nblk) bs[tid] = g_blockSums[tid];
    __syncthreads();
    int i = blockIdx.x * blockDim.x + tid;
    if (i < n) {
        int blk = i >> 10;
        int add = 0;
        for (int j = 0; j < blk; j++) add += bs[j];
        int off = g_offs[i] + add;
        g_offs[i] = off;
        g_cursor[i] = off;
        g_dinv[i] = rsqrtf((float)g_degcnt[i] + 1.0f);
    }
}

__global__ void fill_edges(const int* __restrict__ ei, int e) {
    int idx = blockIdx.x * blockDim.x + threadIdx.x;
    if (idx >= e) return;
    int r = ei[idx];
    int c = ei[idx + e];
    if (r != c) {
        int p = atomicAdd(&g_cursor[c], 1);
        g_edge[p] = make_int2(r, __float_as_int(g_dinv[r] * g_dinv[c]));
    }
}

// ---------------- shared prep helper: fold BN into next conv W ----------------
__device__ void prep_conv_dev(const float* __restrict__ Wc, const float* __restrict__ g,
                              const float* __restrict__ b, float inv_n, int tid) {
    __shared__ float scale[HH], beta[HH];
    if (tid < HH) {
        float m = g_sum[tid] * inv_n;
        float v = g_sumsq[tid] * inv_n - m * m;
        float s = rsqrtf(v + EPS) * g[tid];
        scale[tid] = s;
        beta[tid]  = b[tid] - m * s;
    }
    __syncthreads();
    for (int i = tid; i < HH * HH; i += 256) g_Wc[i] = scale[i >> 6] * Wc[i];
    if (tid < HH) {
        float c = 0.f;
        for (int k = 0; k < HH; k++) c += beta[k] * Wc[k * HH + tid];
        g_c2[tid] = c;
        g_sum[tid] = 0.f;
        g_sumsq[tid] = 0.f;
    }
    if (tid == 0) g_ticket = 0;
}

// ---------------- stats over x (float4 per thread) + last-block prep of g_Wp/g_c1 ----------------
__global__ __launch_bounds__(256) void stats_prep_x(const float* __restrict__ x, int n,
        const float* __restrict__ Wf, const float* __restrict__ g, const float* __restrict__ b,
        float inv_n) {
    __shared__ float red[8][FF];
    __shared__ int isLast;
    int tid = threadIdx.x;
    int l4 = tid & 31;
    int rg = tid >> 5;
    float s0 = 0.f, s1 = 0.f, s2 = 0.f, s3 = 0.f;
    float q0 = 0.f, q1 = 0.f, q2 = 0.f, q3 = 0.f;
    for (int row = blockIdx.x * 8 + rg; row < n; row += gridDim.x * 8) {
        float4 v = ((const float4*)(x + (size_t)row * FF))[l4];
        s0 += v.x; q0 += v.x * v.x;
        s1 += v.y; q1 += v.y * v.y;
        s2 += v.z; q2 += v.z * v.z;
        s3 += v.w; q3 += v.w * v.w;
    }
    red[rg][l4 * 4 + 0] = s0; red[rg][l4 * 4 + 1] = s1;
    red[rg][l4 * 4 + 2] = s2; red[rg][l4 * 4 + 3] = s3;
    __syncthreads();
    if (tid < FF) {
        float s = 0.f;
        for (int r = 0; r < 8; r++) s += red[r][tid];
        atomicAdd(&g_sum[tid], s);
    }
    __syncthreads();
    red[rg][l4 * 4 + 0] = q0; red[rg][l4 * 4 + 1] = q1;
    red[rg][l4 * 4 + 2] = q2; red[rg][l4 * 4 + 3] = q3;
    __syncthreads();
    if (tid < FF) {
        float q = 0.f;
        for (int r = 0; r < 8; r++) q += red[r][tid];
        atomicAdd(&g_sumsq[tid], q);
    }
    __threadfence();
    __syncthreads();
    if (tid == 0) isLast = (atomicAdd(&g_ticket, 1) == (int)gridDim.x - 1);
    __syncthreads();
    if (!isLast) return;
    __shared__ float scale[FF], beta[FF];
    if (tid < FF) {
        float m = g_sum[tid] * inv_n;
        float va = g_sumsq[tid] * inv_n - m * m;
        float sc = rsqrtf(va + EPS) * g[tid];
        scale[tid] = sc;
        beta[tid]  = b[tid] - m * sc;
    }
    __syncthreads();
    for (int i = tid; i < FF * HH; i += 256) g_Wp[i] = scale[i >> 6] * Wf[i];
    if (tid < HH) {
        float c = 0.f;
        for (int k = 0; k < FF; k++) c += beta[k] * Wf[k * HH + tid];
        g_c1[tid] = c;
    }
    if (tid < FF) { g_sum[tid] = 0.f; g_sumsq[tid] = 0.f; }
    if (tid == 0) g_ticket = 0;
}

// ---------------- mm_feat: col-packed tiles; fp16 output; fused stats + prep(conv0) ----------------
__global__ __launch_bounds__(256) void mm_feat(const float* __restrict__ x, int n,
        const float* __restrict__ Wnext, const float* __restrict__ bn_g,
        const float* __restrict__ bn_b, float inv_n) {
    extern __shared__ float smem[];
    float* xs = smem;                 // [128][130]
    float* ws = smem + 128 * 130;     // [128][64]
    __shared__ float red[16][HH];
    __shared__ int isLast;
    u32* out = g_hh1;
    int tid = threadIdx.x;
    int r0 = blockIdx.x * 128;

    for (int i = tid; i < 128 * 16; i += 256)
        ((float4*)ws)[i] = ((const float4*)g_Wp)[i];
    for (int p = 0; p < 32; p++) {
        int idx = p * 256 + tid;
        int row = idx >> 6;
        int f2 = idx & 63;
        float2 v = make_float2(0.f, 0.f);
        if (r0 + row < n) v = ((const float2*)(x + (size_t)(r0 + row) * FF))[f2];
        *(float2*)(xs + row * 130 + f2 * 2) = v;
    }
    __syncthreads();

    int w = tid >> 5;
    int lane = tid & 31;
    int half = lane >> 4;
    int li = lane & 15;
    int c0 = li * 4;
    int rowbase = w * 16 + half * 8;

    ull acc[8][2];
    {
        ull cb0 = *(const ull*)(g_c1 + c0);
        ull cb1 = *(const ull*)(g_c1 + c0 + 2);
#pragma unroll
        for (int r = 0; r < 8; r++) { acc[r][0] = cb0; acc[r][1] = cb1; }
    }
    const float* xrow = xs + rowbase * 130;
    for (int k = 0; k < 128; k++) {
        float4 wv = *(const float4*)(ws + k * 64 + c0);
        ull w0 = pack2(wv.x, wv.y);
        ull w1 = pack2(wv.z, wv.w);
#pragma unroll
        for (int r = 0; r < 8; r++) {
            ull xv = packdup(xrow[r * 130 + k]);
            acc[r][0] = fma2(xv, w0, acc[r][0]);
            acc[r][1] = fma2(xv, w1, acc[r][1]);
        }
    }
    float s0 = 0.f, s1 = 0.f, s2 = 0.f, s3 = 0.f;
    float q0 = 0.f, q1 = 0.f, q2 = 0.f, q3 = 0.f;
#pragma unroll
    for (int r = 0; r < 8; r++) {
        int row = r0 + rowbase + r;
        float v0, v1, v2, v3;
        unpack2(acc[r][0], v0, v1);
        unpack2(acc[r][1], v2, v3);
        v0 = fmaxf(v0, 0.f); v1 = fmaxf(v1, 0.f);
        v2 = fmaxf(v2, 0.f); v3 = fmaxf(v3, 0.f);
        if (row < n) {
            __half2 pa = __floats2half2_rn(v0, v1);
            __half2 pb = __floats2half2_rn(v2, v3);
            uint2 st = make_uint2(*(u32*)&pa, *(u32*)&pb);
            *(uint2*)(out + (size_t)row * 32 + li * 2) = st;
            s0 += v0; q0 += v0 * v0; s1 += v1; q1 += v1 * v1;
            s2 += v2; q2 += v2 * v2; s3 += v3; q3 += v3 * v3;
        }
    }
    int rr = w * 2 + half;
    red[rr][c0] = s0; red[rr][c0 + 1] = s1; red[rr][c0 + 2] = s2; red[rr][c0 + 3] = s3;
    __syncthreads();
    if (tid < HH) { float s = 0.f; for (int r = 0; r < 16; r++) s += red[r][tid]; atomicAdd(&g_sum[tid], s); }
    __syncthreads();
    red[rr][c0] = q0; red[rr][c0 + 1] = q1; red[rr][c0 + 2] = q2; red[rr][c0 + 3] = q3;
    __syncthreads();
    if (tid < HH) { float q = 0.f; for (int r = 0; r < 16; r++) q += red[r][tid]; atomicAdd(&g_sumsq[tid], q); }
    __threadfence();
    __syncthreads();
    if (tid == 0) isLast = (atomicAdd(&g_ticket, 1) == (int)gridDim.x - 1);
    __syncthreads();
    if (isLast) prep_conv_dev(Wnext, bn_g, bn_b, inv_n, tid);
}

// ---------------- fused GCN layer: gather(raw fp16 h) -> @g_Wc + sumw*c2 + bias -> relu -> fp16 ----------------
// warp per node; MLP-8 gather of half2 rows (128B/node); matmul epilogue via smem broadcast.
__global__ __launch_bounds__(256) void agg_mm(int isel, int osel, const float* __restrict__ bias,
        int n, int do_stats, const float* __restrict__ Wnext, const float* __restrict__ bn_g,
        const float* __restrict__ bn_b, float inv_n) {
    __shared__ float asmem[8][65];
    __shared__ float ss[8][HH];
    __shared__ float sq[8][HH];
    __shared__ int isLast;
    int tid = threadIdx.x;
    int lane = tid & 31;
    int w = tid >> 5;
    int v = blockIdx.x * 8 + w;
    const u32* __restrict__ hh = buf16(isel);
    u32* outp = buf16(osel);

    float ax = 0.f, ay = 0.f, sumw = 0.f;
    if (v < n) {
        float dv = g_dinv[v];
        float sl = dv * dv;
        float2 f = h2f(hh[(size_t)v * 32 + lane]);
        ax = sl * f.x; ay = sl * f.y; sumw = sl;
        int s = g_offs[v];
        int cnt = g_counts[v];
        const int2* __restrict__ ge = g_edge + s;
        int j = 0;
        for (; j + 8 <= cnt; j += 8) {
            int2 e0 = ge[j + 0], e1 = ge[j + 1], e2 = ge[j + 2], e3 = ge[j + 3];
            int2 e4 = ge[j + 4], e5 = ge[j + 5], e6 = ge[j + 6], e7 = ge[j + 7];
            u32 h0 = hh[(size_t)e0.x * 32 + lane];
            u32 h1 = hh[(size_t)e1.x * 32 + lane];
            u32 h2 = hh[(size_t)e2.x * 32 + lane];
            u32 h3 = hh[(size_t)e3.x * 32 + lane];
            u32 h4 = hh[(size_t)e4.x * 32 + lane];
            u32 h5 = hh[(size_t)e5.x * 32 + lane];
            u32 h6 = hh[(size_t)e6.x * 32 + lane];
            u32 h7 = hh[(size_t)e7.x * 32 + lane];
            float w0 = __int_as_float(e0.y), w1 = __int_as_float(e1.y);
            float w2 = __int_as_float(e2.y), w3 = __int_as_float(e3.y);
            float w4 = __int_as_float(e4.y), w5 = __int_as_float(e5.y);
            float w6 = __int_as_float(e6.y), w7 = __int_as_float(e7.y);
            float2 f0 = h2f(h0), f1 = h2f(h1), f2 = h2f(h2), f3 = h2f(h3);
            float2 f4 = h2f(h4), f5 = h2f(h5), f6 = h2f(h6), f7 = h2f(h7);
            ax += w0 * f0.x; ay += w0 * f0.y;
            ax += w1 * f1.x; ay += w1 * f1.y;
            ax += w2 * f2.x; ay += w2 * f2.y;
            ax += w3 * f3.x; ay += w3 * f3.y;
            ax += w4 * f4.x; ay += w4 * f4.y;
            ax += w5 * f5.x; ay += w5 * f5.y;
            ax += w6 * f6.x; ay += w6 * f6.y;
            ax += w7 * f7.x; ay += w7 * f7.y;
            sumw += w0 + w1 + w2 + w3 + w4 + w5 + w6 + w7;
        }
        for (; j < cnt; j++) {
            int2 e = ge[j];
            float ww = __int_as_float(e.y);
            float2 f2v = h2f(hh[(size_t)e.x * 32 + lane]);
            ax += ww * f2v.x; ay += ww * f2v.y;
            sumw += ww;
        }
    }
    asmem[w][2 * lane] = ax;
    asmem[w][2 * lane + 1] = ay;
    __syncthreads();

    // matmul epilogue: warp w computes node v's 64 outputs (lane -> cols 2l, 2l+1)
    float y0 = 0.f, y1 = 0.f;
    {
        const ull* __restrict__ W2 = (const ull*)g_Wc;
        ull acc = pack2(0.f, 0.f);
        const float* arow = asmem[w];
#pragma unroll 8
        for (int k = 0; k < 64; k++)
            acc = fma2(packdup(arow[k]), W2[k * 32 + lane], acc);
        float m0, m1;
        unpack2(acc, m0, m1);
        float cc0 = g_c2[2 * lane], cc1 = g_c2[2 * lane + 1];
        if (v < n) {
            y0 = fmaxf(m0 + sumw * cc0 + bias[2 * lane], 0.f);
            y1 = fmaxf(m1 + sumw * cc1 + bias[2 * lane + 1], 0.f);
            __half2 p = __floats2half2_rn(y0, y1);
            outp[(size_t)v * 32 + lane] = *(u32*)&p;
        }
    }
    if (!do_stats) return;
    ss[w][2 * lane] = y0;      ss[w][2 * lane + 1] = y1;
    sq[w][2 * lane] = y0 * y0; sq[w][2 * lane + 1] = y1 * y1;
    __syncthreads();
    if (tid < HH) {
        float s = 0.f, q = 0.f;
        for (int r = 0; r < 8; r++) { s += ss[r][tid]; q += sq[r][tid]; }
        atomicAdd(&g_sum[tid], s);
        atomicAdd(&g_sumsq[tid], q);
    }
    __threadfence();
    __syncthreads();
    if (tid == 0) isLast = (atomicAdd(&g_ticket, 1) == (int)gridDim.x - 1);
    __syncthreads();
    if (isLast) prep_conv_dev(Wnext, bn_g, bn_b, inv_n, tid);
}

// ---------------- pooling over sorted batch (fp16 input) ----------------
#define POOL_CHUNK 128
__global__ void pool_kernel(int isel, const int* __restrict__ batch, int n) {
    const __half* h = (const __half*)buf16(isel);
    int j = threadIdx.x;
    int start = blockIdx.x * POOL_CHUNK;
    int end = min(start + POOL_CHUNK, n);
    if (start >= end) return;
    int cur = batch[start];
    float acc = 0.f;
    for (int r = start; r < end; r++) {
        int gid = batch[r];
        if (gid != cur) {
            atomicAdd(&g_hg[cur * HH + j], acc);
            acc = 0.f;
            cur = gid;
        }
        acc += __half2float(h[(size_t)r * HH + j]);
    }
    atomicAdd(&g_hg[cur * HH + j], acc);
}

// ---------------- head ----------------
__global__ void head_kernel(const float* __restrict__ Wfc, const float* __restrict__ bfc,
                            const float* __restrict__ Wcls, const float* __restrict__ bcls,
                            const float* __restrict__ fg, const float* __restrict__ fb,
                            const float* __restrict__ hg, const float* __restrict__ hb,
                            float* __restrict__ out) {
    __shared__ float sh[GG * HH];
    __shared__ float mcol[HH], rcol[HH];
    int t = threadIdx.x;

    for (int i = t; i < GG * HH; i += blockDim.x) sh[i] = g_hg[i];
    __syncthreads();

    if (t < HH) {
        float s = 0.f, q = 0.f;
        for (int r = 0; r < GG; r++) { float v = sh[r * HH + t]; s += v; q += v * v; }
        float m = s / (float)GG;
        float var = q / (float)GG - m * m;
        mcol[t] = m; rcol[t] = rsqrtf(var + EPS);
    }
    __syncthreads();
    for (int i = t; i < GG * HH; i += blockDim.x) {
        int c = i & (HH - 1);
        sh[i] = (sh[i] - mcol[c]) * rcol[c] * fg[c] + fb[c];
    }
    __syncthreads();

    float y[32];
    int r = t & 127;
    int j0 = (t >> 7) * 32;
    for (int jj = 0; jj < 32; jj++) {
        float a = bfc[j0 + jj];
        for (int k = 0; k < HH; k++) a += sh[r * HH + k] * Wfc[k * HH + j0 + jj];
        y[jj] = fmaxf(a, 0.f);
    }
    __syncthreads();
    for (int jj = 0; jj < 32; jj++) sh[r * HH + j0 + jj] = y[jj];
    __syncthreads();

    if (t < HH) {
        float s = 0.f, q = 0.f;
        for (int rr = 0; rr < GG; rr++) { float v = sh[rr * HH + t]; s += v; q += v * v; }
        float m = s / (float)GG;
        float var = q / (float)GG - m * m;
        mcol[t] = m; rcol[t] = rsqrtf(var + EPS);
    }
    __syncthreads();
    for (int i = t; i < GG * HH; i += blockDim.x) {
        int c = i & (HH - 1);
        sh[i] = (sh[i] - mcol[c]) * rcol[c] * hg[c] + hb[c];
    }
    __syncthreads();

    if (t < GG) {
        for (int c = 0; c < CC; c++) {
            float a = bcls[c];
            for (int k = 0; k < HH; k++) a += sh[t * HH + k] * Wcls[k * CC + c];
            out[t * CC + c] = a;
        }
    }
}

// ---------------- host ----------------
extern "C" void kernel_launch(void* const* d_in, const int* in_sizes, int n_in,
                              void* d_out, int out_size) {
    const float* x     = (const float*)d_in[0];
    const int*   ei    = (const int*)d_in[1];
    const int*   batch = (const int*)d_in[2];

    int base = n_in - 15;
    const float* W_feat  = (const float*)d_in[base + 0];
    const float* W_conv  = (const float*)d_in[base + 1];
    const float* b_conv  = (const float*)d_in[base + 2];
    const float* W_fc    = (const float*)d_in[base + 3];
    const float* b_fc    = (const float*)d_in[base + 4];
    const float* W_cls   = (const float*)d_in[base + 5];
    const float* b_cls   = (const float*)d_in[base + 6];
    const float* bnf_g   = (const float*)d_in[base + 7];
    const float* bnf_b   = (const float*)d_in[base + 8];
    const float* bnc_g   = (const float*)d_in[base + 9];
    const float* bnc_b   = (const float*)d_in[base + 10];
    const float* bnfc_g  = (const float*)d_in[base + 11];
    const float* bnfc_b  = (const float*)d_in[base + 12];
    const float* bnh_g   = (const float*)d_in[base + 13];
    const float* bnh_b   = (const float*)d_in[base + 14];
    float* out = (float*)d_out;

    int n = in_sizes[0] / FF;     // 100000
    int e = in_sizes[1] / 2;      // 1600000
    float inv_n = 1.0f / (float)n;

    int feat_smem = 128 * 130 * 4 + 128 * 64 * 4;   // 99,328 B
    cudaFuncSetAttribute(mm_feat, cudaFuncAttributeMaxDynamicSharedMemorySize, feat_smem);

    int mmb = (n + 127) / 128;
    int aggb = (n + 7) / 8;
    int nblk = (n + 1023) / 1024;

    // Launch order keeps mm_feat at slot 4 (= ncu capture).
    zero_all<<<256, 256>>>(n);
    stats_prep_x<<<512, 256>>>(x, n, W_feat, bnf_g, bnf_b, inv_n);
    edge_count<<<(e + 255) / 256, 256>>>(ei, e);
    mm_feat<<<mmb, 256, feat_smem>>>(x, n, W_conv, bnc_g, bnc_b, inv_n);   // captured

    scan_blocks<<<nblk, 1024>>>(n);
    scan_add<<<(n + 255) / 256, 256>>>(n, nblk);
    fill_edges<<<(e + 255) / 256, 256>>>(ei, e);

    // --- 3 fused GCN layers (gather + matmul + relu + stats/prep) ---
    agg_mm<<<aggb, 256>>>(0, 1, b_conv + 0,   n, 1, W_conv + 4096, bnc_g + 64,  bnc_b + 64,  inv_n);
    agg_mm<<<aggb, 256>>>(1, 0, b_conv + 64,  n, 1, W_conv + 8192, bnc_g + 128, bnc_b + 128, inv_n);
    agg_mm<<<aggb, 256>>>(0, 1, b_conv + 128, n, 0, (const float*)0, (const float*)0, (const float*)0, inv_n);

    // --- pool + head ---
    pool_kernel<<<(n + POOL_CHUNK - 1) / POOL_CHUNK, HH>>>(1, batch, n);
    head_kernel<<<1, 256>>>(W_fc, b_fc, W_cls, b_cls,
                            bnfc_g, bnfc_b, bnh_g, bnh_b, out);
}

// round 15
// speedup vs baseline: 1.2513x; 1.0693x over previous
#include <cuda_runtime.h>
#include <cstdint>

#define NN 100000
#define EE 1600000
#define FF 128
#define HH 64
#define GG 128
#define CC 10
#define EPS 1e-5f
#define FULLMASK 0xffffffffu

typedef unsigned long long ull;

// ---------------- device scratch ----------------
__device__ __align__(16) float g_h1[NN * HH];
__device__ __align__(16) float g_h2[NN * HH];
__device__ int   g_degcnt[NN];
__device__ int   g_counts[NN];
__device__ int   g_offs[NN];
__device__ int   g_cursor[NN];
__device__ float g_dinv[NN];
__device__ __align__(8) int2 g_edge[EE];        // {src, weight-bits}
__device__ int   g_blockSums[128];
__device__ float g_sum[FF];
__device__ float g_sumsq[FF];
__device__ __align__(16) float g_Wp[FF * HH];
__device__ __align__(16) float g_c1[HH];
__device__ __align__(16) float g_Wc[HH * HH];
__device__ __align__(16) float g_c2[HH];
__device__ __align__(16) float g_hg[GG * HH];
__device__ int   g_ticket;

__device__ __forceinline__ float* buf(int sel) { return sel ? g_h2 : g_h1; }

// ---------------- f32x2 packed helpers ----------------
__device__ __forceinline__ ull pack2(float a, float b) {
    ull r; asm("mov.b64 %0, {%1, %2};" : "=l"(r) : "f"(a), "f"(b)); return r;
}
__device__ __forceinline__ ull packdup(float a) {
    ull r; asm("mov.b64 %0, {%1, %1};" : "=l"(r) : "f"(a)); return r;
}
__device__ __forceinline__ void unpack2(ull v, float& a, float& b) {
    asm("mov.b64 {%0, %1}, %2;" : "=f"(a), "=f"(b) : "l"(v));
}
__device__ __forceinline__ ull fma2(ull a, ull b, ull c) {
    ull d; asm("fma.rn.f32x2 %0, %1, %2, %3;" : "=l"(d) : "l"(a), "l"(b), "l"(c)); return d;
}

// ---------------- init ----------------
__global__ void zero_all(int n) {
    int i = blockIdx.x * blockDim.x + threadIdx.x;
    int st = gridDim.x * blockDim.x;
    for (int k = i; k < n; k += st) { g_degcnt[k] = 0; g_counts[k] = 0; }
    for (int k = i; k < GG * HH; k += st) g_hg[k] = 0.f;
    for (int k = i; k < FF; k += st) { g_sum[k] = 0.f; g_sumsq[k] = 0.f; }
    if (i == 0) g_ticket = 0;
}

// ---------------- CSR build (int32 indices) ----------------
__global__ void edge_count(const int* __restrict__ ei, int e) {
    int idx = blockIdx.x * blockDim.x + threadIdx.x;
    if (idx >= e) return;
    int r = ei[idx];
    int c = ei[idx + e];
    if (r != c) {
        atomicAdd(&g_degcnt[r], 1);
        atomicAdd(&g_counts[c], 1);
    }
}

__global__ void scan_blocks(int n) {
    __shared__ int tmp[1024];
    int i = blockIdx.x * 1024 + threadIdx.x;
    int v = (i < n) ? g_counts[i] : 0;
    tmp[threadIdx.x] = v;
    __syncthreads();
    for (int d = 1; d < 1024; d <<= 1) {
        int t = (threadIdx.x >= d) ? tmp[threadIdx.x - d] : 0;
        __syncthreads();
        tmp[threadIdx.x] += t;
        __syncthreads();
    }
    if (i < n) g_offs[i] = tmp[threadIdx.x] - v;
    if (threadIdx.x == 1023) g_blockSums[blockIdx.x] = tmp[1023];
}

__global__ void scan_add(int n, int nblk) {
    __shared__ int bs[128];
    int tid = threadIdx.x;
    if (tid < nblk) bs[tid] = g_blockSums[tid];
    __syncthreads();
    int i = blockIdx.x * blockDim.x + tid;
    if (i < n) {
        int blk = i >> 10;
        int add = 0;
        for (int j = 0; j < blk; j++) add += bs[j];
        int off = g_offs[i] + add;
        g_offs[i] = off;
        g_cursor[i] = off;
        g_dinv[i] = rsqrtf((float)g_degcnt[i] + 1.0f);
    }
}

__global__ void fill_edges(const int* __restrict__ ei, int e) {
    int idx = blockIdx.x * blockDim.x + threadIdx.x;
    if (idx >= e) return;
    int r = ei[idx];
    int c = ei[idx + e];
    if (r != c) {
        int p = atomicAdd(&g_cursor[c], 1);
        g_edge[p] = make_int2(r, __float_as_int(g_dinv[r] * g_dinv[c]));
    }
}

// ---------------- shared prep helper: fold BN into next conv W ----------------
__device__ void prep_conv_dev(const float* __restrict__ Wc, const float* __restrict__ g,
                              const float* __restrict__ b, float inv_n, int tid) {
    __shared__ float scale[HH], beta[HH];
    if (tid < HH) {
        float m = g_sum[tid] * inv_n;
        float v = g_sumsq[tid] * inv_n - m * m;
        float s = rsqrtf(v + EPS) * g[tid];
        scale[tid] = s;
        beta[tid]  = b[tid] - m * s;
    }
    __syncthreads();
    for (int i = tid; i < HH * HH; i += 256) g_Wc[i] = scale[i >> 6] * Wc[i];
    if (tid < HH) {
        float c = 0.f;
        for (int k = 0; k < HH; k++) c += beta[k] * Wc[k * HH + tid];
        g_c2[tid] = c;
        g_sum[tid] = 0.f;
        g_sumsq[tid] = 0.f;
    }
    if (tid == 0) g_ticket = 0;
}

// ---------------- stats over x (float4 per thread) + last-block prep of g_Wp/g_c1 ----------------
__global__ __launch_bounds__(256) void stats_prep_x(const float* __restrict__ x, int n,
        const float* __restrict__ Wf, const float* __restrict__ g, const float* __restrict__ b,
        float inv_n) {
    __shared__ float red[8][FF];
    __shared__ int isLast;
    int tid = threadIdx.x;
    int l4 = tid & 31;
    int rg = tid >> 5;
    float s0 = 0.f, s1 = 0.f, s2 = 0.f, s3 = 0.f;
    float q0 = 0.f, q1 = 0.f, q2 = 0.f, q3 = 0.f;
    for (int row = blockIdx.x * 8 + rg; row < n; row += gridDim.x * 8) {
        float4 v = ((const float4*)(x + (size_t)row * FF))[l4];
        s0 += v.x; q0 += v.x * v.x;
        s1 += v.y; q1 += v.y * v.y;
        s2 += v.z; q2 += v.z * v.z;
        s3 += v.w; q3 += v.w * v.w;
    }
    red[rg][l4 * 4 + 0] = s0; red[rg][l4 * 4 + 1] = s1;
    red[rg][l4 * 4 + 2] = s2; red[rg][l4 * 4 + 3] = s3;
    __syncthreads();
    if (tid < FF) {
        float s = 0.f;
        for (int r = 0; r < 8; r++) s += red[r][tid];
        atomicAdd(&g_sum[tid], s);
    }
    __syncthreads();
    red[rg][l4 * 4 + 0] = q0; red[rg][l4 * 4 + 1] = q1;
    red[rg][l4 * 4 + 2] = q2; red[rg][l4 * 4 + 3] = q3;
    __syncthreads();
    if (tid < FF) {
        float q = 0.f;
        for (int r = 0; r < 8; r++) q += red[r][tid];
        atomicAdd(&g_sumsq[tid], q);
    }
    __threadfence();
    __syncthreads();
    if (tid == 0) isLast = (atomicAdd(&g_ticket, 1) == (int)gridDim.x - 1);
    __syncthreads();
    if (!isLast) return;
    __shared__ float scale[FF], beta[FF];
    if (tid < FF) {
        float m = g_sum[tid] * inv_n;
        float va = g_sumsq[tid] * inv_n - m * m;
        float sc = rsqrtf(va + EPS) * g[tid];
        scale[tid] = sc;
        beta[tid]  = b[tid] - m * sc;
    }
    __syncthreads();
    for (int i = tid; i < FF * HH; i += 256) g_Wp[i] = scale[i >> 6] * Wf[i];
    if (tid < HH) {
        float c = 0.f;
        for (int k = 0; k < FF; k++) c += beta[k] * Wf[k * HH + tid];
        g_c1[tid] = c;
    }
    if (tid < FF) { g_sum[tid] = 0.f; g_sumsq[tid] = 0.f; }
    if (tid == 0) g_ticket = 0;
}

// ---------------- mm_feat: col-packed, broadcast-x tiles; fp32 out; fused stats + prep(conv0) ----------------
__global__ __launch_bounds__(256) void mm_feat(const float* __restrict__ x, int n,
        const float* __restrict__ Wnext, const float* __restrict__ bn_g,
        const float* __restrict__ bn_b, float inv_n) {
    extern __shared__ float smem[];
    float* xs = smem;                 // [128][130]
    float* ws = smem + 128 * 130;     // [128][64]
    __shared__ float red[16][HH];
    __shared__ int isLast;
    float* out = g_h1;
    int tid = threadIdx.x;
    int r0 = blockIdx.x * 128;

    for (int i = tid; i < 128 * 16; i += 256)
        ((float4*)ws)[i] = ((const float4*)g_Wp)[i];
    for (int p = 0; p < 32; p++) {
        int idx = p * 256 + tid;
        int row = idx >> 6;
        int f2 = idx & 63;
        float2 v = make_float2(0.f, 0.f);
        if (r0 + row < n) v = ((const float2*)(x + (size_t)(r0 + row) * FF))[f2];
        *(float2*)(xs + row * 130 + f2 * 2) = v;
    }
    __syncthreads();

    int w = tid >> 5;
    int lane = tid & 31;
    int half = lane >> 4;
    int li = lane & 15;
    int c0 = li * 4;
    int rowbase = w * 16 + half * 8;

    ull acc[8][2];
    {
        ull cb0 = *(const ull*)(g_c1 + c0);
        ull cb1 = *(const ull*)(g_c1 + c0 + 2);
#pragma unroll
        for (int r = 0; r < 8; r++) { acc[r][0] = cb0; acc[r][1] = cb1; }
    }
    const float* xrow = xs + rowbase * 130;
    for (int k = 0; k < 128; k++) {
        float4 wv = *(const float4*)(ws + k * 64 + c0);
        ull w0 = pack2(wv.x, wv.y);
        ull w1 = pack2(wv.z, wv.w);
#pragma unroll
        for (int r = 0; r < 8; r++) {
            ull xv = packdup(xrow[r * 130 + k]);
            acc[r][0] = fma2(xv, w0, acc[r][0]);
            acc[r][1] = fma2(xv, w1, acc[r][1]);
        }
    }
    float s0 = 0.f, s1 = 0.f, s2 = 0.f, s3 = 0.f;
    float q0 = 0.f, q1 = 0.f, q2 = 0.f, q3 = 0.f;
#pragma unroll
    for (int r = 0; r < 8; r++) {
        int row = r0 + rowbase + r;
        float v0, v1, v2, v3;
        unpack2(acc[r][0], v0, v1);
        unpack2(acc[r][1], v2, v3);
        v0 = fmaxf(v0, 0.f); v1 = fmaxf(v1, 0.f);
        v2 = fmaxf(v2, 0.f); v3 = fmaxf(v3, 0.f);
        if (row < n) {
            *(ull*)(out + (size_t)row * HH + c0)     = pack2(v0, v1);
            *(ull*)(out + (size_t)row * HH + c0 + 2) = pack2(v2, v3);
            s0 += v0; q0 += v0 * v0; s1 += v1; q1 += v1 * v1;
            s2 += v2; q2 += v2 * v2; s3 += v3; q3 += v3 * v3;
        }
    }
    int rr = w * 2 + half;
    red[rr][c0] = s0; red[rr][c0 + 1] = s1; red[rr][c0 + 2] = s2; red[rr][c0 + 3] = s3;
    __syncthreads();
    if (tid < HH) { float s = 0.f; for (int r = 0; r < 16; r++) s += red[r][tid]; atomicAdd(&g_sum[tid], s); }
    __syncthreads();
    red[rr][c0] = q0; red[rr][c0 + 1] = q1; red[rr][c0 + 2] = q2; red[rr][c0 + 3] = q3;
    __syncthreads();
    if (tid < HH) { float q = 0.f; for (int r = 0; r < 16; r++) q += red[r][tid]; atomicAdd(&g_sumsq[tid], q); }
    __threadfence();
    __syncthreads();
    if (tid == 0) isLast = (atomicAdd(&g_ticket, 1) == (int)gridDim.x - 1);
    __syncthreads();
    if (isLast) prep_conv_dev(Wnext, bn_g, bn_b, inv_n, tid);
}

// ---------------- fused GCN layer: 4 nodes/warp; gather fp32 -> smem -> @Wc(smem) + sumw*c2 + bias -> relu ----------------
__global__ __launch_bounds__(256) void agg_mm(int isel, int osel, const float* __restrict__ bias,
        int n, int do_stats, const float* __restrict__ Wnext, const float* __restrict__ bn_g,
        const float* __restrict__ bn_b, float inv_n) {
    __shared__ float wsm[HH * HH];       // 16 KB: folded W for this layer
    __shared__ float asmem[32][66];      // per-node aggregated features (+sumw at [64])
    __shared__ float ss[8][HH];
    __shared__ float sq[8][HH];
    __shared__ int isLast;
    int tid = threadIdx.x;
    int lane = tid & 31;
    int w = tid >> 5;
    int vbase = blockIdx.x * 32 + w * 4;
    const ull* __restrict__ hh = (const ull*)buf(isel);
    float* outp = buf(osel);

    // cooperative W load (overlaps with gather issue below via separate smem region)
    for (int i = tid; i < HH * HH / 4; i += 256)
        ((float4*)wsm)[i] = ((const float4*)g_Wc)[i];

    // gather phase: 4 nodes per warp
    for (int i = 0; i < 4; i++) {
        int v = vbase + i;
        float ax = 0.f, ay = 0.f, sumw = 0.f;
        if (v < n) {
            float dv = g_dinv[v];
            float sl = dv * dv;
            float hx, hy;
            unpack2(hh[(size_t)v * 32 + lane], hx, hy);
            ull acc0 = pack2(hx * sl, hy * sl);
            ull acc1 = pack2(0.f, 0.f);
            sumw = sl;
            int s = g_offs[v];
            int cnt = g_counts[v];
            const int2* __restrict__ ge = g_edge + s;
            int j = 0;
            for (; j + 8 <= cnt; j += 8) {
                int2 e0 = ge[j + 0], e1 = ge[j + 1], e2 = ge[j + 2], e3 = ge[j + 3];
                int2 e4 = ge[j + 4], e5 = ge[j + 5], e6 = ge[j + 6], e7 = ge[j + 7];
                ull h0 = hh[(size_t)e0.x * 32 + lane];
                ull h1 = hh[(size_t)e1.x * 32 + lane];
                ull h2 = hh[(size_t)e2.x * 32 + lane];
                ull h3 = hh[(size_t)e3.x * 32 + lane];
                ull h4 = hh[(size_t)e4.x * 32 + lane];
                ull h5 = hh[(size_t)e5.x * 32 + lane];
                ull h6 = hh[(size_t)e6.x * 32 + lane];
                ull h7 = hh[(size_t)e7.x * 32 + lane];
                float w0 = __int_as_float(e0.y), w1 = __int_as_float(e1.y);
                float w2 = __int_as_float(e2.y), w3 = __int_as_float(e3.y);
                float w4 = __int_as_float(e4.y), w5 = __int_as_float(e5.y);
                float w6 = __int_as_float(e6.y), w7 = __int_as_float(e7.y);
                acc0 = fma2(h0, packdup(w0), acc0);
                acc1 = fma2(h1, packdup(w1), acc1);
                acc0 = fma2(h2, packdup(w2), acc0);
                acc1 = fma2(h3, packdup(w3), acc1);
                acc0 = fma2(h4, packdup(w4), acc0);
                acc1 = fma2(h5, packdup(w5), acc1);
                acc0 = fma2(h6, packdup(w6), acc0);
                acc1 = fma2(h7, packdup(w7), acc1);
                sumw += w0 + w1 + w2 + w3 + w4 + w5 + w6 + w7;
            }
            for (; j < cnt; j++) {
                int2 e = ge[j];
                float ww = __int_as_float(e.y);
                acc0 = fma2(hh[(size_t)e.x * 32 + lane], packdup(ww), acc0);
                sumw += ww;
            }
            float a0x, a0y, a1x, a1y;
            unpack2(acc0, a0x, a0y);
            unpack2(acc1, a1x, a1y);
            ax = a0x + a1x;
            ay = a0y + a1y;
        }
        asmem[w * 4 + i][2 * lane] = ax;
        asmem[w * 4 + i][2 * lane + 1] = ay;
        if (lane == 0) asmem[w * 4 + i][64] = sumw;   // warp-uniform
    }
    __syncthreads();   // wsm ready + asmem visible

    // epilogue: matmul per node (lane -> cols 2l, 2l+1), per-thread stats over 4 nodes
    float cc0 = g_c2[2 * lane], cc1 = g_c2[2 * lane + 1];
    float b0 = bias[2 * lane], b1 = bias[2 * lane + 1];
    float s0 = 0.f, s1 = 0.f, q0 = 0.f, q1 = 0.f;
    for (int i = 0; i < 4; i++) {
        int v = vbase + i;
        const float* arow = asmem[w * 4 + i];
        float sumw = arow[64];
        ull acc = pack2(0.f, 0.f);
#pragma unroll 8
        for (int k = 0; k < 64; k++)
            acc = fma2(packdup(arow[k]), *(const ull*)(wsm + k * 64 + 2 * lane), acc);
        float m0, m1;
        unpack2(acc, m0, m1);
        if (v < n) {
            float y0 = fmaxf(m0 + sumw * cc0 + b0, 0.f);
            float y1 = fmaxf(m1 + sumw * cc1 + b1, 0.f);
            *(ull*)(outp + (size_t)v * HH + 2 * lane) = pack2(y0, y1);
            s0 += y0; q0 += y0 * y0;
            s1 += y1; q1 += y1 * y1;
        }
    }
    if (!do_stats) return;
    ss[w][2 * lane] = s0; ss[w][2 * lane + 1] = s1;
    sq[w][2 * lane] = q0; sq[w][2 * lane + 1] = q1;
    __syncthreads();
    if (tid < HH) {
        float s = 0.f, q = 0.f;
        for (int r = 0; r < 8; r++) { s += ss[r][tid]; q += sq[r][tid]; }
        atomicAdd(&g_sum[tid], s);
        atomicAdd(&g_sumsq[tid], q);
    }
    __threadfence();
    __syncthreads();
    if (tid == 0) isLast = (atomicAdd(&g_ticket, 1) == (int)gridDim.x - 1);
    __syncthreads();
    if (isLast) prep_conv_dev(Wnext, bn_g, bn_b, inv_n, tid);
}

// ---------------- pooling over sorted batch ----------------
#define POOL_CHUNK 128
__global__ void pool_kernel(int isel, const int* __restrict__ batch, int n) {
    const float* h = buf(isel);
    int j = threadIdx.x;
    int start = blockIdx.x * POOL_CHUNK;
    int end = min(start + POOL_CHUNK, n);
    if (start >= end) return;
    int cur = batch[start];
    float acc = 0.f;
    for (int r = start; r < end; r++) {
        int gid = batch[r];
        if (gid != cur) {
            atomicAdd(&g_hg[cur * HH + j], acc);
            acc = 0.f;
            cur = gid;
        }
        acc += h[(size_t)r * HH + j];
    }
    atomicAdd(&g_hg[cur * HH + j], acc);
}

// ---------------- head ----------------
__global__ void head_kernel(const float* __restrict__ Wfc, const float* __restrict__ bfc,
                            const float* __restrict__ Wcls, const float* __restrict__ bcls,
                            const float* __restrict__ fg, const float* __restrict__ fb,
                            const float* __restrict__ hg, const float* __restrict__ hb,
                            float* __restrict__ out) {
    __shared__ float sh[GG * HH];
    __shared__ float mcol[HH], rcol[HH];
    int t = threadIdx.x;

    for (int i = t; i < GG * HH; i += blockDim.x) sh[i] = g_hg[i];
    __syncthreads();

    if (t < HH) {
        float s = 0.f, q = 0.f;
        for (int r = 0; r < GG; r++) { float v = sh[r * HH + t]; s += v; q += v * v; }
        float m = s / (float)GG;
        float var = q / (float)GG - m * m;
        mcol[t] = m; rcol[t] = rsqrtf(var + EPS);
    }
    __syncthreads();
    for (int i = t; i < GG * HH; i += blockDim.x) {
        int c = i & (HH - 1);
        sh[i] = (sh[i] - mcol[c]) * rcol[c] * fg[c] + fb[c];
    }
    __syncthreads();

    float y[32];
    int r = t & 127;
    int j0 = (t >> 7) * 32;
    for (int jj = 0; jj < 32; jj++) {
        float a = bfc[j0 + jj];
        for (int k = 0; k < HH; k++) a += sh[r * HH + k] * Wfc[k * HH + j0 + jj];
        y[jj] = fmaxf(a, 0.f);
    }
    __syncthreads();
    for (int jj = 0; jj < 32; jj++) sh[r * HH + j0 + jj] = y[jj];
    __syncthreads();

    if (t < HH) {
        float s = 0.f, q = 0.f;
        for (int rr = 0; rr < GG; rr++) { float v = sh[rr * HH + t]; s += v; q += v * v; }
        float m = s / (float)GG;
        float var = q / (float)GG - m * m;
        mcol[t] = m; rcol[t] = rsqrtf(var + EPS);
    }
    __syncthreads();
    for (int i = t; i < GG * HH; i += blockDim.x) {
        int c = i & (HH - 1);
        sh[i] = (sh[i] - mcol[c]) * rcol[c] * hg[c] + hb[c];
    }
    __syncthreads();

    if (t < GG) {
        for (int c = 0; c < CC; c++) {
            float a = bcls[c];
            for (int k = 0; k < HH; k++) a += sh[t * HH + k] * Wcls[k * CC + c];
            out[t * CC + c] = a;
        }
    }
}

// ---------------- host ----------------
extern "C" void kernel_launch(void* const* d_in, const int* in_sizes, int n_in,
                              void* d_out, int out_size) {
    const float* x     = (const float*)d_in[0];
    const int*   ei    = (const int*)d_in[1];
    const int*   batch = (const int*)d_in[2];

    int base = n_in - 15;
    const float* W_feat  = (const float*)d_in[base + 0];
    const float* W_conv  = (const float*)d_in[base + 1];
    const float* b_conv  = (const float*)d_in[base + 2];
    const float* W_fc    = (const float*)d_in[base + 3];
    const float* b_fc    = (const float*)d_in[base + 4];
    const float* W_cls   = (const float*)d_in[base + 5];
    const float* b_cls   = (const float*)d_in[base + 6];
    const float* bnf_g   = (const float*)d_in[base + 7];
    const float* bnf_b   = (const float*)d_in[base + 8];
    const float* bnc_g   = (const float*)d_in[base + 9];
    const float* bnc_b   = (const float*)d_in[base + 10];
    const float* bnfc_g  = (const float*)d_in[base + 11];
    const float* bnfc_b  = (const float*)d_in[base + 12];
    const float* bnh_g   = (const float*)d_in[base + 13];
    const float* bnh_b   = (const float*)d_in[base + 14];
    float* out = (float*)d_out;

    int n = in_sizes[0] / FF;     // 100000
    int e = in_sizes[1] / 2;      // 1600000
    float inv_n = 1.0f / (float)n;

    int feat_smem = 128 * 130 * 4 + 128 * 64 * 4;   // 99,328 B
    cudaFuncSetAttribute(mm_feat, cudaFuncAttributeMaxDynamicSharedMemorySize, feat_smem);

    int mmb = (n + 127) / 128;
    int aggb = (n + 31) / 32;     // 4 nodes per warp, 8 warps per block
    int nblk = (n + 1023) / 1024;

    // Launch order keeps mm_feat at slot 4 (= ncu capture).
    zero_all<<<256, 256>>>(n);
    stats_prep_x<<<512, 256>>>(x, n, W_feat, bnf_g, bnf_b, inv_n);
    edge_count<<<(e + 255) / 256, 256>>>(ei, e);
    mm_feat<<<mmb, 256, feat_smem>>>(x, n, W_conv, bnc_g, bnc_b, inv_n);   // captured

    scan_blocks<<<nblk, 1024>>>(n);
    scan_add<<<(n + 255) / 256, 256>>>(n, nblk);
    fill_edges<<<(e + 255) / 256, 256>>>(ei, e);

    // --- 3 fused GCN layers (gather + matmul + relu + stats/prep) ---
    agg_mm<<<aggb, 256>>>(0, 1, b_conv + 0,   n, 1, W_conv + 4096, bnc_g + 64,  bnc_b + 64,  inv_n);
    agg_mm<<<aggb, 256>>>(1, 0, b_conv + 64,  n, 1, W_conv + 8192, bnc_g + 128, bnc_b + 128, inv_n);
    agg_mm<<<aggb, 256>>>(0, 1, b_conv + 128, n, 0, (const float*)0, (const float*)0, (const float*)0, inv_n);

    // --- pool + head ---
    pool_kernel<<<(n + POOL_CHUNK - 1) / POOL_CHUNK, HH>>>(1, batch, n);
    head_kernel<<<1, 256>>>(W_fc, b_fc, W_cls, b_cls,
                            bnfc_g, bnfc_b, bnh_g, bnh_b, out);
}